// round 12
// baseline (speedup 1.0000x reference)
#include <cuda_runtime.h>
#include <cuda_fp16.h>
#include <cstdint>
#include <math.h>

#define HH 128
#define WW 128
#define HWs (HH*WW)
#define CC 64
#define BB 8
#define KK 9
#define CK 576

// Scratch (device globals: allocation-free kernel_launch)
__device__ __half g_xh[(size_t)BB * HWs * CC];       // NHWC fp16 copy of x
__device__ float  g_offmask[(size_t)BB * HWs * 27];  // [b][pix][k][{offy,offx,mask}]
__device__ __half g_acth[(size_t)BB * HWs * CC];     // NHWC fp16 leaky output
__device__ __half g_wdcH[9 * 64 * 64];               // [tap][oc][c], fp16
__device__ __half g_wcH[9 * 64 * 64];                // [tap][oc][c], fp16
__device__ float  g_womT[9 * 32 * 64];               // [tap][oc(27 pad32)][c], tf32

// ---------------------------------------------------------------------------
__device__ __forceinline__ float to_tf32(float f) {
    uint32_t u;
    asm("cvt.rna.tf32.f32 %0, %1;" : "=r"(u) : "f"(f));
    return __uint_as_float(u);
}

__device__ __forceinline__ void mma8(float4& d, const uint32_t* a, const uint32_t* bf) {
    asm volatile(
        "mma.sync.aligned.m16n8k8.row.col.f32.tf32.tf32.f32 "
        "{%0,%1,%2,%3},{%4,%5,%6,%7},{%8,%9},{%0,%1,%2,%3};\n"
        : "+f"(d.x), "+f"(d.y), "+f"(d.z), "+f"(d.w)
        : "r"(a[0]), "r"(a[1]), "r"(a[2]), "r"(a[3]), "r"(bf[0]), "r"(bf[1]));
}

__device__ __forceinline__ void mma16(float4& d, const uint32_t* a, const uint32_t* bf) {
    asm volatile(
        "mma.sync.aligned.m16n8k16.row.col.f32.f16.f16.f32 "
        "{%0,%1,%2,%3},{%4,%5,%6,%7},{%8,%9},{%0,%1,%2,%3};\n"
        : "+f"(d.x), "+f"(d.y), "+f"(d.z), "+f"(d.w)
        : "r"(a[0]), "r"(a[1]), "r"(a[2]), "r"(a[3]), "r"(bf[0]), "r"(bf[1]));
}

// ---------------------------------------------------------------------------
// Kernel W: weights -> [tap][oc][c] fp16 (dc, c) and tf32 (om)
// ---------------------------------------------------------------------------
__global__ __launch_bounds__(256) void wtrans_kernel(const float* __restrict__ w_dc,
                                                     const float* __restrict__ w_c,
                                                     const float* __restrict__ w_om) {
    int i = blockIdx.x * 256 + threadIdx.x;
    if (i < 36864) {
        int tap = i >> 12, rem = i & 4095, o = rem >> 6, c = rem & 63;
        g_wdcH[i] = __float2half(w_dc[o * 576 + c * 9 + tap]);
    } else if (i < 73728) {
        int j = i - 36864;
        int tap = j >> 12, rem = j & 4095, o = rem >> 6, c = rem & 63;
        g_wcH[j] = __float2half(w_c[o * 576 + c * 9 + tap]);
    } else if (i < 92160) {
        int j = i - 73728;
        int tap = j >> 11, rem = j & 2047, o = rem >> 6, c = rem & 63;
        g_womT[j] = (o < 27) ? to_tf32(w_om[o * 576 + c * 9 + tap]) : 0.f;
    }
}

// ---------------------------------------------------------------------------
// Kernel T: NCHW fp32 -> NHWC fp16
// ---------------------------------------------------------------------------
__global__ __launch_bounds__(256) void transpose_kernel(const float* __restrict__ x) {
    __shared__ float t[64 * 65];
    int tid = threadIdx.x;
    int blk = blockIdx.x;
    int b  = blk >> 8;
    int p0 = (blk & 255) * 64;

    #pragma unroll
    for (int i = tid; i < 4096; i += 256) {
        int c  = i >> 6;
        int pl = i & 63;
        t[pl * 65 + c] = x[((size_t)b * CC + c) * HWs + p0 + pl];
    }
    __syncthreads();
    #pragma unroll
    for (int i = tid; i < 2048; i += 256) {
        int pl = i >> 5;
        int cp = i & 31;
        __half2 v = __floats2half2_rn(t[pl * 65 + 2 * cp], t[pl * 65 + 2 * cp + 1]);
        *(__half2*)(g_xh + ((size_t)b * HWs + p0 + pl) * CC + 2 * cp) = v;
    }
}

// ---------------------------------------------------------------------------
// Kernel A: offsets+mask conv via tf32 tensor cores (fp32 path, unchanged).
// ---------------------------------------------------------------------------
#define OM_SMEM_BYTES ((64*136 + 2*32*68) * 4)
__global__ __launch_bounds__(256, 2) void offmask_tc(const float* __restrict__ x,
                                                     const float* __restrict__ b_om) {
    extern __shared__ float sm[];
    float* sval = sm;              // [64][136]
    float* swk  = sm + 64 * 136;   // [2][32][68]

    int tid = threadIdx.x;
    int b = blockIdx.x >> 7;
    int h = blockIdx.x & 127;

    int lane = tid & 31, wid = tid >> 5;
    int warp_m = wid & 3;
    int warp_n = wid >> 2;
    int lq = lane >> 2, lr = lane & 3;

    float4 acc[2][2];
    #pragma unroll
    for (int mt = 0; mt < 2; ++mt)
        #pragma unroll
        for (int nt = 0; nt < 2; ++nt) acc[mt][nt] = make_float4(0.f, 0.f, 0.f, 0.f);

    #pragma unroll
    for (int r = 0; r < 2; ++r) {
        int idx = tid + 256 * r;
        int o = idx >> 4, cq = idx & 15;
        *(float4*)&swk[o * 68 + cq * 4] = *(const float4*)&g_womT[idx * 4];
    }

    #pragma unroll 1
    for (int dy = 0; dy < 3; ++dy) {
        if (dy) __syncthreads();
        int y = h - 1 + dy;
        bool yok = (y >= 0) & (y < HH);
        const float* xrow = x + (size_t)b * CC * HWs + (size_t)y * WW;
        {
            int ch = tid >> 7, j = tid & 127;
            int xg = j - 1;
            #pragma unroll
            for (int c0 = 0; c0 < 64; c0 += 2) {
                int c = c0 + ch;
                float v = (yok && xg >= 0) ? __ldg(xrow + (size_t)c * HWs + xg) : 0.f;
                sval[c * 136 + j] = to_tf32(v);
            }
            if (tid < 128) {
                int c = tid >> 1, jj = 128 + (tid & 1);
                float v = (yok && jj < 129) ? __ldg(xrow + (size_t)c * HWs + jj - 1) : 0.f;
                sval[c * 136 + jj] = to_tf32(v);
            }
        }
        #pragma unroll
        for (int dx = 0; dx < 3; ++dx) {
            int t = dy * 3 + dx;
            __syncthreads();
            if (t < 8) {
                int nb = (t + 1) & 1;
                #pragma unroll
                for (int r = 0; r < 2; ++r) {
                    int idx = tid + 256 * r;
                    int o = idx >> 4, cq = idx & 15;
                    *(float4*)&swk[nb * 2176 + o * 68 + cq * 4] =
                        *(const float4*)&g_womT[(t + 1) * 2048 + idx * 4];
                }
            }
            const float* wb = swk + (t & 1) * 2176;
            #pragma unroll
            for (int k0 = 0; k0 < 64; k0 += 8) {
                uint32_t afr[2][4];
                #pragma unroll
                for (int mt = 0; mt < 2; ++mt) {
                    int pxb = warp_m * 32 + mt * 16 + lq + dx;
                    afr[mt][0] = __float_as_uint(sval[(k0 + lr) * 136 + pxb]);
                    afr[mt][1] = __float_as_uint(sval[(k0 + lr) * 136 + pxb + 8]);
                    afr[mt][2] = __float_as_uint(sval[(k0 + lr + 4) * 136 + pxb]);
                    afr[mt][3] = __float_as_uint(sval[(k0 + lr + 4) * 136 + pxb + 8]);
                }
                uint32_t bfr[2][2];
                #pragma unroll
                for (int nt = 0; nt < 2; ++nt) {
                    int oc = warp_n * 16 + nt * 8 + lq;
                    bfr[nt][0] = __float_as_uint(wb[oc * 68 + k0 + lr]);
                    bfr[nt][1] = __float_as_uint(wb[oc * 68 + k0 + lr + 4]);
                }
                #pragma unroll
                for (int mt = 0; mt < 2; ++mt)
                    #pragma unroll
                    for (int nt = 0; nt < 2; ++nt)
                        mma8(acc[mt][nt], afr[mt], bfr[nt]);
            }
        }
    }

    __syncthreads();
    float* outs = sm;
    #pragma unroll
    for (int mt = 0; mt < 2; ++mt) {
        #pragma unroll
        for (int nt = 0; nt < 2; ++nt) {
            int px = warp_m * 32 + mt * 16 + lq;
            int oc = warp_n * 16 + nt * 8 + 2 * lr;
            float4 v = acc[mt][nt];
            outs[oc * 136 + px]           = v.x;
            outs[(oc + 1) * 136 + px]     = v.y;
            outs[oc * 136 + px + 8]       = v.z;
            outs[(oc + 1) * 136 + px + 8] = v.w;
        }
    }
    __syncthreads();
    float* dst = g_offmask + ((size_t)b * HWs + h * WW) * 27;
    for (int idx = tid; idx < 128 * 27; idx += 256) {
        int px = idx / 27, e = idx - px * 27;
        int k = e / 3, r = e - 3 * k;
        int src = (r < 2) ? (2 * k + r) : (18 + k);
        float v = outs[src * 136 + px] + __ldg(b_om + src);
        if (r == 2) v = 2.f / (1.f + expf(-v));
        dst[px * 27 + e] = v;
    }
}

// ---------------------------------------------------------------------------
// deform gather (fp16, R8 per-thread form): thread = (pixel pg, channel octet
// oct). One LDG.128 per corner, bilinear in fp32, one STS.128 out.
// dst row stride 136 halves; writes at column oct*8 (caller offsets by tap).
// ---------------------------------------------------------------------------
__device__ __forceinline__ void dgather32h(const __half* __restrict__ xb,
                                           const float* __restrict__ omrow,
                                           __half* __restrict__ dst,
                                           int h, int w0, int tap,
                                           int pg, int oct) {
    int ty = h - 1 + tap / 3;
    int txoff = tap % 3 - 1;
    const float* o3 = omrow + pg * 27 + tap * 3;
    float offy = __ldg(o3), offx = __ldg(o3 + 1), msk = __ldg(o3 + 2);
    float py = (float)ty + offy;
    float px = (float)(w0 + pg + txoff) + offx;
    float y0f = floorf(py), x0f = floorf(px);
    float ly = py - y0f, lx = px - x0f;
    int y0 = (int)y0f, x0 = (int)x0f;
    float wq[4] = {(1.f - ly) * (1.f - lx) * msk, (1.f - ly) * lx * msk,
                   ly * (1.f - lx) * msk,          ly * lx * msk};
    int ys[2] = {y0, y0 + 1};
    int xs[2] = {x0, x0 + 1};
    bool yok[2] = {(y0 >= 0) & (y0 < HH), (y0 + 1 >= 0) & (y0 + 1 < HH)};
    bool xok[2] = {(x0 >= 0) & (x0 < WW), (x0 + 1 >= 0) & (x0 + 1 < WW)};

    float u[8];
    #pragma unroll
    for (int j = 0; j < 8; ++j) u[j] = 0.f;

    #pragma unroll
    for (int sy = 0; sy < 2; ++sy) {
        #pragma unroll
        for (int sx = 0; sx < 2; ++sx) {
            if (yok[sy] && xok[sx]) {
                uint4 raw = __ldg((const uint4*)(xb +
                    ((size_t)(ys[sy] * WW + xs[sx])) * CC + oct * 8));
                float w = wq[sy * 2 + sx];
                const __half2* hp = (const __half2*)&raw;
                #pragma unroll
                for (int q = 0; q < 4; ++q) {
                    float2 f = __half22float2(hp[q]);
                    u[2 * q]     += w * f.x;
                    u[2 * q + 1] += w * f.y;
                }
            }
        }
    }
    __align__(16) __half2 p[4];
    #pragma unroll
    for (int q = 0; q < 4; ++q) p[q] = __floats2half2_rn(u[2 * q], u[2 * q + 1]);
    *(uint4*)&dst[pg * 136 + oct * 8] = *(const uint4*)p;
}

// ---------------------------------------------------------------------------
// Kernel B: modulated deformable conv 64->64, fp16 m16n8k16 tensor cores.
// 32-px tiles (4096 blocks), 4 blocks/SM. Taps processed in PAIRS (K=128 per
// phase): 5 phases, one sync each. Tap-9 slot zero-filled (MMA-neutral).
// sval [2][32px][136h], swk [2][64oc][136h]. Warp tile 16px x 16oc.
// ---------------------------------------------------------------------------
#define B_SMEM_BYTES ((2*32*136 + 2*64*136) * 2)
__global__ __launch_bounds__(256, 4) void deform_kernel(const float* __restrict__ b_dc) {
    extern __shared__ __half smh[];
    __half* sval = smh;                  // [2][32][136]
    __half* swk  = smh + 2 * 32 * 136;   // [2][64][136]

    int tid = threadIdx.x;
    int blk = blockIdx.x;
    int b = blk >> 9;
    int rem = blk & 511;
    int h = rem >> 2;
    int w0 = (rem & 3) * 32;

    int lane = tid & 31, wid = tid >> 5;
    int warp_m = wid & 1;                // 2 x 16 px
    int warp_n = wid >> 1;               // 4 x 16 oc
    int lq = lane >> 2, lr = lane & 3;

    int oct = tid & 7;                   // channel octet (8 ch)
    int pg  = tid >> 3;                  // pixel 0..31
    const __half* xb = g_xh + (size_t)b * HWs * CC;
    const float* omrow = g_offmask + ((size_t)b * HWs + h * WW + w0) * 27;

    float4 acc[2];
    acc[0] = make_float4(0.f, 0.f, 0.f, 0.f);
    acc[1] = make_float4(0.f, 0.f, 0.f, 0.f);

    const uint4 zero4 = make_uint4(0u, 0u, 0u, 0u);

    // staging helper work: taps (2*ph, 2*ph+1) -> buffer `buf`
    auto stage_phase = [&](int ph, int buf) {
        __half* sv = sval + buf * 32 * 136;
        __half* wk = swk + buf * 64 * 136;
        #pragma unroll
        for (int s = 0; s < 2; ++s) {
            int t = 2 * ph + s;
            // weights: 4096 halves = 512 uint4
            #pragma unroll
            for (int r = 0; r < 2; ++r) {
                int idx = tid + 256 * r;
                int o = idx >> 3, seg = idx & 7;
                uint4 v = (t < 9) ? ((const uint4*)g_wdcH)[t * 512 + idx] : zero4;
                *(uint4*)&wk[o * 136 + s * 64 + seg * 8] = v;
            }
            // gather
            if (t < 9)
                dgather32h(xb, omrow, sv + s * 64, h, w0, t, pg, oct);
            else
                *(uint4*)&sv[s * 64 + pg * 136 + oct * 8] = zero4;
        }
    };

    // prologue: phase 0 (taps 0,1)
    stage_phase(0, 0);
    __syncthreads();

    #pragma unroll 1
    for (int ph = 0; ph < 5; ++ph) {
        int cur = ph & 1, nxt = cur ^ 1;
        bool pre = ph < 4;

        const uint32_t* svw = (const uint32_t*)(sval + cur * 32 * 136);
        const uint32_t* wbw = (const uint32_t*)(swk + cur * 64 * 136);
        int pxb = warp_m * 16 + lq;
        #pragma unroll
        for (int ks = 0; ks < 8; ++ks) {
            uint32_t a[4];
            a[0] = svw[pxb * 68 + ks * 8 + lr];
            a[1] = svw[(pxb + 8) * 68 + ks * 8 + lr];
            a[2] = svw[pxb * 68 + ks * 8 + lr + 4];
            a[3] = svw[(pxb + 8) * 68 + ks * 8 + lr + 4];
            #pragma unroll
            for (int nt = 0; nt < 2; ++nt) {
                int oc = warp_n * 16 + nt * 8 + lq;
                uint32_t bw[2];
                bw[0] = wbw[oc * 68 + ks * 8 + lr];
                bw[1] = wbw[oc * 68 + ks * 8 + lr + 4];
                mma16(acc[nt], a, bw);
            }
        }

        if (pre) stage_phase(ph + 1, nxt);
        __syncthreads();
    }

    // epilogue: bias + LeakyReLU -> outs [32px][72oc] fp16, then NHWC store
    __half* outs = smh;   // reuse sval region (needs 2304 halves)
    {
        int px = warp_m * 16 + lq;
        #pragma unroll
        for (int nt = 0; nt < 2; ++nt) {
            int oc = warp_n * 16 + nt * 8 + 2 * lr;
            float b0 = __ldg(b_dc + oc), b1 = __ldg(b_dc + oc + 1);
            float4 v = acc[nt];
            float e0 = v.x + b0, e1 = v.y + b1, e2 = v.z + b0, e3 = v.w + b1;
            e0 = e0 > 0.f ? e0 : 0.2f * e0;
            e1 = e1 > 0.f ? e1 : 0.2f * e1;
            e2 = e2 > 0.f ? e2 : 0.2f * e2;
            e3 = e3 > 0.f ? e3 : 0.2f * e3;
            *(__half2*)&outs[px * 72 + oc]       = __floats2half2_rn(e0, e1);
            *(__half2*)&outs[(px + 8) * 72 + oc] = __floats2half2_rn(e2, e3);
        }
    }
    __syncthreads();
    {
        int p = tid >> 3, seg = tid & 7;
        uint4 v = *(const uint4*)&outs[p * 72 + seg * 8];
        *(uint4*)(g_acth + ((size_t)b * HWs + h * WW + w0 + p) * CC + seg * 8) = v;
    }
}

// ---------------------------------------------------------------------------
// Kernel C: 3x3 conv 64->64 on fp16 NHWC act, fp16 m16n8k16 tensor cores.
// 128-px row blocks, one sync/tap pipeline, bias + fp32 residual epilogue.
// sval [2][136px][72h], swk [2][64oc][72h].  (R8 version, proven)
// ---------------------------------------------------------------------------
#define C_SMEM_BYTES ((2*136*72 + 2*64*72) * 2)
__global__ __launch_bounds__(256, 3) void conv2_kernel(const float* __restrict__ x,
                                                       const float* __restrict__ b_c,
                                                       float* __restrict__ out) {
    extern __shared__ __half smh[];
    __half* sval = smh;                  // [2][136][72]
    __half* swk  = smh + 2 * 136 * 72;   // [2][64][72]

    int tid = threadIdx.x;
    int b = blockIdx.x >> 7;
    int h = blockIdx.x & 127;

    int lane = tid & 31, wid = tid >> 5;
    int warp_m = wid & 3;                // 4 x 32 px
    int warp_n = wid >> 2;               // 2 x 32 oc
    int lq = lane >> 2, lr = lane & 3;

    float4 acc[2][4];
    #pragma unroll
    for (int mt = 0; mt < 2; ++mt)
        #pragma unroll
        for (int nt = 0; nt < 4; ++nt) acc[mt][nt] = make_float4(0.f, 0.f, 0.f, 0.f);

    const __half* actb = g_acth + (size_t)b * HWs * CC;

    // row stager: sval[buf][j][c] = act[y][j-1][c], j in 0..129
    auto stage_row = [&](int y, __half* dstv) {
        bool yok = (y >= 0) & (y < HH);
        #pragma unroll
        for (int r = 0; r < 5; ++r) {
            int i = tid + 256 * r;
            if (i < 1040) {
                int jj = i >> 3, o = i & 7;
                int xg = jj - 1;
                uint4 v = make_uint4(0u, 0u, 0u, 0u);
                if (yok && xg >= 0 && xg < WW)
                    v = __ldg((const uint4*)(actb + ((size_t)y * WW + xg) * CC + o * 8));
                *(uint4*)&dstv[jj * 72 + o * 8] = v;
            }
        }
    };

    // prologue: row dy=0 into buf0, tap0 weights into wbuf0
    stage_row(h - 1, sval);
    #pragma unroll
    for (int r = 0; r < 2; ++r) {
        int idx = tid + 256 * r;
        ((uint4*)swk)[(idx >> 3) * 9 + (idx & 7)] = ((const uint4*)g_wcH)[idx];
    }
    __syncthreads();

    #pragma unroll 1
    for (int t = 0; t < KK; ++t) {
        int dy = t / 3, dx = t % 3;
        int wcur = t & 1, wnxt = wcur ^ 1;
        int abuf = dy & 1;
        bool pre = t < 8;

        const uint32_t* svw = (const uint32_t*)(sval + abuf * 136 * 72);
        const uint32_t* wbw = (const uint32_t*)(swk + wcur * 64 * 72);
        #pragma unroll
        for (int ks = 0; ks < 4; ++ks) {
            uint32_t a[2][4];
            #pragma unroll
            for (int mt = 0; mt < 2; ++mt) {
                int pxb = warp_m * 32 + mt * 16 + lq + dx;
                a[mt][0] = svw[pxb * 36 + ks * 8 + lr];
                a[mt][1] = svw[(pxb + 8) * 36 + ks * 8 + lr];
                a[mt][2] = svw[pxb * 36 + ks * 8 + lr + 4];
                a[mt][3] = svw[(pxb + 8) * 36 + ks * 8 + lr + 4];
            }
            uint32_t bw[4][2];
            #pragma unroll
            for (int nt = 0; nt < 4; ++nt) {
                int oc = warp_n * 32 + nt * 8 + lq;
                bw[nt][0] = wbw[oc * 36 + ks * 8 + lr];
                bw[nt][1] = wbw[oc * 36 + ks * 8 + lr + 4];
            }
            #pragma unroll
            for (int mt = 0; mt < 2; ++mt)
                #pragma unroll
                for (int nt = 0; nt < 4; ++nt)
                    mma16(acc[mt][nt], a[mt], bw[nt]);
        }

        if (dx == 0 && dy < 2)
            stage_row(h + dy, sval + (abuf ^ 1) * 136 * 72);
        if (pre) {
            #pragma unroll
            for (int r = 0; r < 2; ++r) {
                int idx = tid + 256 * r;
                ((uint4*)(swk + wnxt * 64 * 72))[(idx >> 3) * 9 + (idx & 7)] =
                    ((const uint4*)g_wcH)[(t + 1) * 512 + idx];
            }
        }
        __syncthreads();
    }

    // epilogue: bias, transpose via smem (fp32), residual + coalesced store
    float* outs = (float*)smh;   // [64 oc][136 px] = 34.8KB, fits sval region
    #pragma unroll
    for (int mt = 0; mt < 2; ++mt) {
        #pragma unroll
        for (int nt = 0; nt < 4; ++nt) {
            int px = warp_m * 32 + mt * 16 + lq;
            int oc = warp_n * 32 + nt * 8 + 2 * lr;
            float b0 = __ldg(b_c + oc), b1 = __ldg(b_c + oc + 1);
            float4 v = acc[mt][nt];
            outs[oc * 136 + px]           = v.x + b0;
            outs[(oc + 1) * 136 + px]     = v.y + b1;
            outs[oc * 136 + px + 8]       = v.z + b0;
            outs[(oc + 1) * 136 + px + 8] = v.w + b1;
        }
    }
    __syncthreads();
    #pragma unroll
    for (int j2 = 0; j2 < 8; ++j2) {
        int idx = tid + 256 * j2;
        int oc = idx >> 5, pxq = idx & 31;
        size_t base = ((size_t)b * CC + oc) * HWs + h * WW + pxq * 4;
        float4 v = *(const float4*)&outs[oc * 136 + pxq * 4];
        float4 r = *(const float4*)(x + base);
        v.x += r.x; v.y += r.y; v.z += r.z; v.w += r.w;
        *(float4*)(out + base) = v;
    }
}

// ---------------------------------------------------------------------------
extern "C" void kernel_launch(void* const* d_in, const int* in_sizes, int n_in,
                              void* d_out, int out_size) {
    const float* x    = (const float*)d_in[0];
    const float* w_om = (const float*)d_in[1];
    const float* b_om = (const float*)d_in[2];
    const float* w_dc = (const float*)d_in[3];
    const float* b_dc = (const float*)d_in[4];
    const float* w_c  = (const float*)d_in[5];
    const float* b_c  = (const float*)d_in[6];
    float* out = (float*)d_out;

    cudaFuncSetAttribute(offmask_tc, cudaFuncAttributeMaxDynamicSharedMemorySize,
                         OM_SMEM_BYTES);
    cudaFuncSetAttribute(deform_kernel, cudaFuncAttributeMaxDynamicSharedMemorySize,
                         B_SMEM_BYTES);
    cudaFuncSetAttribute(conv2_kernel, cudaFuncAttributeMaxDynamicSharedMemorySize,
                         C_SMEM_BYTES);

    wtrans_kernel<<<360, 256>>>(w_dc, w_c, w_om);
    transpose_kernel<<<BB * (HWs / 64), 256>>>(x);

    offmask_tc<<<BB * HH, 256, OM_SMEM_BYTES>>>(x, b_om);

    deform_kernel<<<BB * HH * 4, 256, B_SMEM_BYTES>>>(b_dc);

    conv2_kernel<<<BB * HH, 256, C_SMEM_BYTES>>>(x, b_c, out);
}

// round 13
// speedup vs baseline: 1.0594x; 1.0594x over previous
#include <cuda_runtime.h>
#include <cuda_fp16.h>
#include <cstdint>
#include <math.h>

#define HH 128
#define WW 128
#define HWs (HH*WW)
#define CC 64
#define BB 8
#define KK 9
#define CK 576

// Scratch (device globals: allocation-free kernel_launch)
__device__ __half g_xh[(size_t)BB * HWs * CC];       // NHWC fp16 copy of x
__device__ float  g_offmask[(size_t)BB * HWs * 27];  // [b][pix][k][{offy,offx,mask}]
__device__ __half g_acth[(size_t)BB * HWs * CC];     // NHWC fp16 leaky output
__device__ __half g_wdcH[9 * 64 * 64];               // [tap][oc][c], fp16
__device__ __half g_wcH[9 * 64 * 64];                // [tap][oc][c], fp16
__device__ float  g_womT[9 * 32 * 64];               // [tap][oc(27 pad32)][c], tf32

// ---------------------------------------------------------------------------
__device__ __forceinline__ float to_tf32(float f) {
    uint32_t u;
    asm("cvt.rna.tf32.f32 %0, %1;" : "=r"(u) : "f"(f));
    return __uint_as_float(u);
}

__device__ __forceinline__ void mma8(float4& d, const uint32_t* a, const uint32_t* bf) {
    asm volatile(
        "mma.sync.aligned.m16n8k8.row.col.f32.tf32.tf32.f32 "
        "{%0,%1,%2,%3},{%4,%5,%6,%7},{%8,%9},{%0,%1,%2,%3};\n"
        : "+f"(d.x), "+f"(d.y), "+f"(d.z), "+f"(d.w)
        : "r"(a[0]), "r"(a[1]), "r"(a[2]), "r"(a[3]), "r"(bf[0]), "r"(bf[1]));
}

__device__ __forceinline__ void mma16(float4& d, const uint32_t* a, const uint32_t* bf) {
    asm volatile(
        "mma.sync.aligned.m16n8k16.row.col.f32.f16.f16.f32 "
        "{%0,%1,%2,%3},{%4,%5,%6,%7},{%8,%9},{%0,%1,%2,%3};\n"
        : "+f"(d.x), "+f"(d.y), "+f"(d.z), "+f"(d.w)
        : "r"(a[0]), "r"(a[1]), "r"(a[2]), "r"(a[3]), "r"(bf[0]), "r"(bf[1]));
}

__device__ __forceinline__ uint32_t smem_u32(const void* p) {
    return (uint32_t)__cvta_generic_to_shared(p);
}

__device__ __forceinline__ void ldsm_x4(uint32_t* r, uint32_t addr) {
    asm volatile("ldmatrix.sync.aligned.m8n8.x4.shared.b16 {%0,%1,%2,%3}, [%4];\n"
        : "=r"(r[0]), "=r"(r[1]), "=r"(r[2]), "=r"(r[3]) : "r"(addr));
}

// ---------------------------------------------------------------------------
// Kernel W: weights -> [tap][oc][c] fp16 (dc, c) and tf32 (om)
// ---------------------------------------------------------------------------
__global__ __launch_bounds__(256) void wtrans_kernel(const float* __restrict__ w_dc,
                                                     const float* __restrict__ w_c,
                                                     const float* __restrict__ w_om) {
    int i = blockIdx.x * 256 + threadIdx.x;
    if (i < 36864) {
        int tap = i >> 12, rem = i & 4095, o = rem >> 6, c = rem & 63;
        g_wdcH[i] = __float2half(w_dc[o * 576 + c * 9 + tap]);
    } else if (i < 73728) {
        int j = i - 36864;
        int tap = j >> 12, rem = j & 4095, o = rem >> 6, c = rem & 63;
        g_wcH[j] = __float2half(w_c[o * 576 + c * 9 + tap]);
    } else if (i < 92160) {
        int j = i - 73728;
        int tap = j >> 11, rem = j & 2047, o = rem >> 6, c = rem & 63;
        g_womT[j] = (o < 27) ? to_tf32(w_om[o * 576 + c * 9 + tap]) : 0.f;
    }
}

// ---------------------------------------------------------------------------
// Kernel T: NCHW fp32 -> NHWC fp16
// ---------------------------------------------------------------------------
__global__ __launch_bounds__(256) void transpose_kernel(const float* __restrict__ x) {
    __shared__ float t[64 * 65];
    int tid = threadIdx.x;
    int blk = blockIdx.x;
    int b  = blk >> 8;
    int p0 = (blk & 255) * 64;

    #pragma unroll
    for (int i = tid; i < 4096; i += 256) {
        int c  = i >> 6;
        int pl = i & 63;
        t[pl * 65 + c] = x[((size_t)b * CC + c) * HWs + p0 + pl];
    }
    __syncthreads();
    #pragma unroll
    for (int i = tid; i < 2048; i += 256) {
        int pl = i >> 5;
        int cp = i & 31;
        __half2 v = __floats2half2_rn(t[pl * 65 + 2 * cp], t[pl * 65 + 2 * cp + 1]);
        *(__half2*)(g_xh + ((size_t)b * HWs + p0 + pl) * CC + 2 * cp) = v;
    }
}

// ---------------------------------------------------------------------------
// Kernel A: offsets+mask conv via tf32 tensor cores (fp32 path, unchanged).
// ---------------------------------------------------------------------------
#define OM_SMEM_BYTES ((64*136 + 2*32*68) * 4)
__global__ __launch_bounds__(256, 2) void offmask_tc(const float* __restrict__ x,
                                                     const float* __restrict__ b_om) {
    extern __shared__ float sm[];
    float* sval = sm;              // [64][136]
    float* swk  = sm + 64 * 136;   // [2][32][68]

    int tid = threadIdx.x;
    int b = blockIdx.x >> 7;
    int h = blockIdx.x & 127;

    int lane = tid & 31, wid = tid >> 5;
    int warp_m = wid & 3;
    int warp_n = wid >> 2;
    int lq = lane >> 2, lr = lane & 3;

    float4 acc[2][2];
    #pragma unroll
    for (int mt = 0; mt < 2; ++mt)
        #pragma unroll
        for (int nt = 0; nt < 2; ++nt) acc[mt][nt] = make_float4(0.f, 0.f, 0.f, 0.f);

    #pragma unroll
    for (int r = 0; r < 2; ++r) {
        int idx = tid + 256 * r;
        int o = idx >> 4, cq = idx & 15;
        *(float4*)&swk[o * 68 + cq * 4] = *(const float4*)&g_womT[idx * 4];
    }

    #pragma unroll 1
    for (int dy = 0; dy < 3; ++dy) {
        if (dy) __syncthreads();
        int y = h - 1 + dy;
        bool yok = (y >= 0) & (y < HH);
        const float* xrow = x + (size_t)b * CC * HWs + (size_t)y * WW;
        {
            int ch = tid >> 7, j = tid & 127;
            int xg = j - 1;
            #pragma unroll
            for (int c0 = 0; c0 < 64; c0 += 2) {
                int c = c0 + ch;
                float v = (yok && xg >= 0) ? __ldg(xrow + (size_t)c * HWs + xg) : 0.f;
                sval[c * 136 + j] = to_tf32(v);
            }
            if (tid < 128) {
                int c = tid >> 1, jj = 128 + (tid & 1);
                float v = (yok && jj < 129) ? __ldg(xrow + (size_t)c * HWs + jj - 1) : 0.f;
                sval[c * 136 + jj] = to_tf32(v);
            }
        }
        #pragma unroll
        for (int dx = 0; dx < 3; ++dx) {
            int t = dy * 3 + dx;
            __syncthreads();
            if (t < 8) {
                int nb = (t + 1) & 1;
                #pragma unroll
                for (int r = 0; r < 2; ++r) {
                    int idx = tid + 256 * r;
                    int o = idx >> 4, cq = idx & 15;
                    *(float4*)&swk[nb * 2176 + o * 68 + cq * 4] =
                        *(const float4*)&g_womT[(t + 1) * 2048 + idx * 4];
                }
            }
            const float* wb = swk + (t & 1) * 2176;
            #pragma unroll
            for (int k0 = 0; k0 < 64; k0 += 8) {
                uint32_t afr[2][4];
                #pragma unroll
                for (int mt = 0; mt < 2; ++mt) {
                    int pxb = warp_m * 32 + mt * 16 + lq + dx;
                    afr[mt][0] = __float_as_uint(sval[(k0 + lr) * 136 + pxb]);
                    afr[mt][1] = __float_as_uint(sval[(k0 + lr) * 136 + pxb + 8]);
                    afr[mt][2] = __float_as_uint(sval[(k0 + lr + 4) * 136 + pxb]);
                    afr[mt][3] = __float_as_uint(sval[(k0 + lr + 4) * 136 + pxb + 8]);
                }
                uint32_t bfr[2][2];
                #pragma unroll
                for (int nt = 0; nt < 2; ++nt) {
                    int oc = warp_n * 16 + nt * 8 + lq;
                    bfr[nt][0] = __float_as_uint(wb[oc * 68 + k0 + lr]);
                    bfr[nt][1] = __float_as_uint(wb[oc * 68 + k0 + lr + 4]);
                }
                #pragma unroll
                for (int mt = 0; mt < 2; ++mt)
                    #pragma unroll
                    for (int nt = 0; nt < 2; ++nt)
                        mma8(acc[mt][nt], afr[mt], bfr[nt]);
            }
        }
    }

    __syncthreads();
    float* outs = sm;
    #pragma unroll
    for (int mt = 0; mt < 2; ++mt) {
        #pragma unroll
        for (int nt = 0; nt < 2; ++nt) {
            int px = warp_m * 32 + mt * 16 + lq;
            int oc = warp_n * 16 + nt * 8 + 2 * lr;
            float4 v = acc[mt][nt];
            outs[oc * 136 + px]           = v.x;
            outs[(oc + 1) * 136 + px]     = v.y;
            outs[oc * 136 + px + 8]       = v.z;
            outs[(oc + 1) * 136 + px + 8] = v.w;
        }
    }
    __syncthreads();
    float* dst = g_offmask + ((size_t)b * HWs + h * WW) * 27;
    for (int idx = tid; idx < 128 * 27; idx += 256) {
        int px = idx / 27, e = idx - px * 27;
        int k = e / 3, r = e - 3 * k;
        int src = (r < 2) ? (2 * k + r) : (18 + k);
        float v = outs[src * 136 + px] + __ldg(b_om + src);
        if (r == 2) v = 2.f / (1.f + expf(-v));
        dst[px * 27 + e] = v;
    }
}

// ---------------------------------------------------------------------------
// deform gather (fp16, R8 per-thread form): thread = (pixel pg, channel octet
// oct). One LDG.128 per corner, bilinear in fp32, one STS.128 out.
// ---------------------------------------------------------------------------
__device__ __forceinline__ void dgather32h(const __half* __restrict__ xb,
                                           const float* __restrict__ omrow,
                                           __half* __restrict__ dst,
                                           int h, int w0, int tap,
                                           int pg, int oct) {
    int ty = h - 1 + tap / 3;
    int txoff = tap % 3 - 1;
    const float* o3 = omrow + pg * 27 + tap * 3;
    float offy = __ldg(o3), offx = __ldg(o3 + 1), msk = __ldg(o3 + 2);
    float py = (float)ty + offy;
    float px = (float)(w0 + pg + txoff) + offx;
    float y0f = floorf(py), x0f = floorf(px);
    float ly = py - y0f, lx = px - x0f;
    int y0 = (int)y0f, x0 = (int)x0f;
    float wq[4] = {(1.f - ly) * (1.f - lx) * msk, (1.f - ly) * lx * msk,
                   ly * (1.f - lx) * msk,          ly * lx * msk};
    int ys[2] = {y0, y0 + 1};
    int xs[2] = {x0, x0 + 1};
    bool yok[2] = {(y0 >= 0) & (y0 < HH), (y0 + 1 >= 0) & (y0 + 1 < HH)};
    bool xok[2] = {(x0 >= 0) & (x0 < WW), (x0 + 1 >= 0) & (x0 + 1 < WW)};

    float u[8];
    #pragma unroll
    for (int j = 0; j < 8; ++j) u[j] = 0.f;

    #pragma unroll
    for (int sy = 0; sy < 2; ++sy) {
        #pragma unroll
        for (int sx = 0; sx < 2; ++sx) {
            if (yok[sy] && xok[sx]) {
                uint4 raw = __ldg((const uint4*)(xb +
                    ((size_t)(ys[sy] * WW + xs[sx])) * CC + oct * 8));
                float w = wq[sy * 2 + sx];
                const __half2* hp = (const __half2*)&raw;
                #pragma unroll
                for (int q = 0; q < 4; ++q) {
                    float2 f = __half22float2(hp[q]);
                    u[2 * q]     += w * f.x;
                    u[2 * q + 1] += w * f.y;
                }
            }
        }
    }
    __align__(16) __half2 p[4];
    #pragma unroll
    for (int q = 0; q < 4; ++q) p[q] = __floats2half2_rn(u[2 * q], u[2 * q + 1]);
    *(uint4*)&dst[pg * 72 + oct * 8] = *(const uint4*)p;
}

// ---------------------------------------------------------------------------
// Kernel B: modulated deformable conv 64->64, fp16 m16n8k16 tensor cores.
// 32-px tiles (4096 blocks), 4 blocks/SM. One sync/tap pipeline (R8), with
// ldmatrix.x4 fragment loads (8 LDSM/warp-tap vs 64 scalar LDS).
// sval [2][32px][72h], swk [2][64oc][72h]. Warp tile 16px x 16oc.
// ---------------------------------------------------------------------------
#define B_SMEM_BYTES ((2*32*72 + 2*64*72) * 2)
__global__ __launch_bounds__(256, 4) void deform_kernel(const float* __restrict__ b_dc) {
    extern __shared__ __half smh[];
    __half* sval = smh;                  // [2][32][72]
    __half* swk  = smh + 2 * 32 * 72;    // [2][64][72]

    int tid = threadIdx.x;
    int blk = blockIdx.x;
    int b = blk >> 9;
    int rem = blk & 511;
    int h = rem >> 2;
    int w0 = (rem & 3) * 32;

    int lane = tid & 31, wid = tid >> 5;
    int warp_m = wid & 1;                // 2 x 16 px
    int warp_n = wid >> 1;               // 4 x 16 oc
    int lq = lane >> 2, lr = lane & 3;

    // ldmatrix lane row/col (A: 16px x 16ch tile; B: 16oc x 16ch tile)
    int aRowL = warp_m * 16 + (lane & 7) + ((lane >> 3) & 1) * 8;
    int aColL = ((lane >> 4) & 1) * 8;
    int bRowL = warp_n * 16 + ((lane >> 4) & 1) * 8 + (lane & 7);
    int bColL = ((lane >> 3) & 1) * 8;

    int oct = tid & 7;                   // channel octet (8 ch)
    int pg  = tid >> 3;                  // pixel 0..31
    const __half* xb = g_xh + (size_t)b * HWs * CC;
    const float* omrow = g_offmask + ((size_t)b * HWs + h * WW + w0) * 27;

    float4 acc[2];
    acc[0] = make_float4(0.f, 0.f, 0.f, 0.f);
    acc[1] = make_float4(0.f, 0.f, 0.f, 0.f);

    // prologue: tap0 weights + gather
    #pragma unroll
    for (int r = 0; r < 2; ++r) {
        int idx = tid + 256 * r;
        ((uint4*)swk)[(idx >> 3) * 9 + (idx & 7)] = ((const uint4*)g_wdcH)[idx];
    }
    dgather32h(xb, omrow, sval, h, w0, 0, pg, oct);
    __syncthreads();

    #pragma unroll 1
    for (int tap = 0; tap < KK; ++tap) {
        int cur = tap & 1, nxt = cur ^ 1;
        bool pre = tap < 8;

        const __half* sv = sval + cur * 32 * 72;
        const __half* wb = swk + cur * 64 * 72;
        uint32_t aAddr = smem_u32(&sv[aRowL * 72 + aColL]);
        uint32_t bAddr = smem_u32(&wb[bRowL * 72 + bColL]);
        #pragma unroll
        for (int ks = 0; ks < 4; ++ks) {
            uint32_t a[4], bq[4];
            ldsm_x4(a, aAddr + ks * 32);     // +16 halves per k-step
            ldsm_x4(bq, bAddr + ks * 32);
            mma16(acc[0], a, bq);            // oc block 0: {k0-7, k8-15}
            mma16(acc[1], a, bq + 2);        // oc block 1
        }

        if (pre) {
            #pragma unroll
            for (int r = 0; r < 2; ++r) {
                int idx = tid + 256 * r;
                ((uint4*)(swk + nxt * 64 * 72))[(idx >> 3) * 9 + (idx & 7)] =
                    ((const uint4*)g_wdcH)[(tap + 1) * 512 + idx];
            }
            dgather32h(xb, omrow, sval + nxt * 32 * 72, h, w0, tap + 1, pg, oct);
        }
        __syncthreads();
    }

    // epilogue: bias + LeakyReLU -> outs [32px][72oc] fp16, then NHWC store
    __half* outs = smh;   // reuse sval region (needs 2304 halves)
    {
        int px = warp_m * 16 + lq;
        #pragma unroll
        for (int nt = 0; nt < 2; ++nt) {
            int oc = warp_n * 16 + nt * 8 + 2 * lr;
            float b0 = __ldg(b_dc + oc), b1 = __ldg(b_dc + oc + 1);
            float4 v = acc[nt];
            float e0 = v.x + b0, e1 = v.y + b1, e2 = v.z + b0, e3 = v.w + b1;
            e0 = e0 > 0.f ? e0 : 0.2f * e0;
            e1 = e1 > 0.f ? e1 : 0.2f * e1;
            e2 = e2 > 0.f ? e2 : 0.2f * e2;
            e3 = e3 > 0.f ? e3 : 0.2f * e3;
            *(__half2*)&outs[px * 72 + oc]       = __floats2half2_rn(e0, e1);
            *(__half2*)&outs[(px + 8) * 72 + oc] = __floats2half2_rn(e2, e3);
        }
    }
    __syncthreads();
    {
        int p = tid >> 3, seg = tid & 7;
        uint4 v = *(const uint4*)&outs[p * 72 + seg * 8];
        *(uint4*)(g_acth + ((size_t)b * HWs + h * WW + w0 + p) * CC + seg * 8) = v;
    }
}

// ---------------------------------------------------------------------------
// Kernel C: 3x3 conv 64->64 on fp16 NHWC act, fp16 m16n8k16 tensor cores.
// 128-px row blocks, one sync/tap pipeline, bias + fp32 residual epilogue.
// sval [2][136px][72h], swk [2][64oc][72h].  (R8 version, proven)
// ---------------------------------------------------------------------------
#define C_SMEM_BYTES ((2*136*72 + 2*64*72) * 2)
__global__ __launch_bounds__(256, 3) void conv2_kernel(const float* __restrict__ x,
                                                       const float* __restrict__ b_c,
                                                       float* __restrict__ out) {
    extern __shared__ __half smh[];
    __half* sval = smh;                  // [2][136][72]
    __half* swk  = smh + 2 * 136 * 72;   // [2][64][72]

    int tid = threadIdx.x;
    int b = blockIdx.x >> 7;
    int h = blockIdx.x & 127;

    int lane = tid & 31, wid = tid >> 5;
    int warp_m = wid & 3;                // 4 x 32 px
    int warp_n = wid >> 2;               // 2 x 32 oc
    int lq = lane >> 2, lr = lane & 3;

    float4 acc[2][4];
    #pragma unroll
    for (int mt = 0; mt < 2; ++mt)
        #pragma unroll
        for (int nt = 0; nt < 4; ++nt) acc[mt][nt] = make_float4(0.f, 0.f, 0.f, 0.f);

    const __half* actb = g_acth + (size_t)b * HWs * CC;

    // row stager: sval[buf][j][c] = act[y][j-1][c], j in 0..129
    auto stage_row = [&](int y, __half* dstv) {
        bool yok = (y >= 0) & (y < HH);
        #pragma unroll
        for (int r = 0; r < 5; ++r) {
            int i = tid + 256 * r;
            if (i < 1040) {
                int jj = i >> 3, o = i & 7;
                int xg = jj - 1;
                uint4 v = make_uint4(0u, 0u, 0u, 0u);
                if (yok && xg >= 0 && xg < WW)
                    v = __ldg((const uint4*)(actb + ((size_t)y * WW + xg) * CC + o * 8));
                *(uint4*)&dstv[jj * 72 + o * 8] = v;
            }
        }
    };

    // prologue: row dy=0 into buf0, tap0 weights into wbuf0
    stage_row(h - 1, sval);
    #pragma unroll
    for (int r = 0; r < 2; ++r) {
        int idx = tid + 256 * r;
        ((uint4*)swk)[(idx >> 3) * 9 + (idx & 7)] = ((const uint4*)g_wcH)[idx];
    }
    __syncthreads();

    #pragma unroll 1
    for (int t = 0; t < KK; ++t) {
        int dy = t / 3, dx = t % 3;
        int wcur = t & 1, wnxt = wcur ^ 1;
        int abuf = dy & 1;
        bool pre = t < 8;

        const uint32_t* svw = (const uint32_t*)(sval + abuf * 136 * 72);
        const uint32_t* wbw = (const uint32_t*)(swk + wcur * 64 * 72);
        #pragma unroll
        for (int ks = 0; ks < 4; ++ks) {
            uint32_t a[2][4];
            #pragma unroll
            for (int mt = 0; mt < 2; ++mt) {
                int pxb = warp_m * 32 + mt * 16 + lq + dx;
                a[mt][0] = svw[pxb * 36 + ks * 8 + lr];
                a[mt][1] = svw[(pxb + 8) * 36 + ks * 8 + lr];
                a[mt][2] = svw[pxb * 36 + ks * 8 + lr + 4];
                a[mt][3] = svw[(pxb + 8) * 36 + ks * 8 + lr + 4];
            }
            uint32_t bw[4][2];
            #pragma unroll
            for (int nt = 0; nt < 4; ++nt) {
                int oc = warp_n * 32 + nt * 8 + lq;
                bw[nt][0] = wbw[oc * 36 + ks * 8 + lr];
                bw[nt][1] = wbw[oc * 36 + ks * 8 + lr + 4];
            }
            #pragma unroll
            for (int mt = 0; mt < 2; ++mt)
                #pragma unroll
                for (int nt = 0; nt < 4; ++nt)
                    mma16(acc[mt][nt], a[mt], bw[nt]);
        }

        if (dx == 0 && dy < 2)
            stage_row(h + dy, sval + (abuf ^ 1) * 136 * 72);
        if (pre) {
            #pragma unroll
            for (int r = 0; r < 2; ++r) {
                int idx = tid + 256 * r;
                ((uint4*)(swk + wnxt * 64 * 72))[(idx >> 3) * 9 + (idx & 7)] =
                    ((const uint4*)g_wcH)[(t + 1) * 512 + idx];
            }
        }
        __syncthreads();
    }

    // epilogue: bias, transpose via smem (fp32), residual + coalesced store
    float* outs = (float*)smh;   // [64 oc][136 px] = 34.8KB, fits sval region
    #pragma unroll
    for (int mt = 0; mt < 2; ++mt) {
        #pragma unroll
        for (int nt = 0; nt < 4; ++nt) {
            int px = warp_m * 32 + mt * 16 + lq;
            int oc = warp_n * 32 + nt * 8 + 2 * lr;
            float b0 = __ldg(b_c + oc), b1 = __ldg(b_c + oc + 1);
            float4 v = acc[mt][nt];
            outs[oc * 136 + px]           = v.x + b0;
            outs[(oc + 1) * 136 + px]     = v.y + b1;
            outs[oc * 136 + px + 8]       = v.z + b0;
            outs[(oc + 1) * 136 + px + 8] = v.w + b1;
        }
    }
    __syncthreads();
    #pragma unroll
    for (int j2 = 0; j2 < 8; ++j2) {
        int idx = tid + 256 * j2;
        int oc = idx >> 5, pxq = idx & 31;
        size_t base = ((size_t)b * CC + oc) * HWs + h * WW + pxq * 4;
        float4 v = *(const float4*)&outs[oc * 136 + pxq * 4];
        float4 r = *(const float4*)(x + base);
        v.x += r.x; v.y += r.y; v.z += r.z; v.w += r.w;
        *(float4*)(out + base) = v;
    }
}

// ---------------------------------------------------------------------------
extern "C" void kernel_launch(void* const* d_in, const int* in_sizes, int n_in,
                              void* d_out, int out_size) {
    const float* x    = (const float*)d_in[0];
    const float* w_om = (const float*)d_in[1];
    const float* b_om = (const float*)d_in[2];
    const float* w_dc = (const float*)d_in[3];
    const float* b_dc = (const float*)d_in[4];
    const float* w_c  = (const float*)d_in[5];
    const float* b_c  = (const float*)d_in[6];
    float* out = (float*)d_out;

    cudaFuncSetAttribute(offmask_tc, cudaFuncAttributeMaxDynamicSharedMemorySize,
                         OM_SMEM_BYTES);
    cudaFuncSetAttribute(deform_kernel, cudaFuncAttributeMaxDynamicSharedMemorySize,
                         B_SMEM_BYTES);
    cudaFuncSetAttribute(conv2_kernel, cudaFuncAttributeMaxDynamicSharedMemorySize,
                         C_SMEM_BYTES);

    wtrans_kernel<<<360, 256>>>(w_dc, w_c, w_om);
    transpose_kernel<<<BB * (HWs / 64), 256>>>(x);

    offmask_tc<<<BB * HH, 256, OM_SMEM_BYTES>>>(x, b_om);

    deform_kernel<<<BB * HH * 4, 256, B_SMEM_BYTES>>>(b_dc);

    conv2_kernel<<<BB * HH, 256, C_SMEM_BYTES>>>(x, b_c, out);
}

// round 14
// speedup vs baseline: 1.2348x; 1.1655x over previous
#include <cuda_runtime.h>
#include <cuda_fp16.h>
#include <cstdint>
#include <math.h>

#define HH 128
#define WW 128
#define HWs (HH*WW)
#define CC 64
#define BB 8
#define KK 9
#define CK 576

// Scratch (device globals: allocation-free kernel_launch)
__device__ __half g_xh[(size_t)BB * HWs * CC];       // NHWC fp16 copy of x
__device__ float  g_offmask[(size_t)BB * HWs * 27];  // [b][pix][k][{offy,offx,mask}]
__device__ __half g_acth[(size_t)BB * HWs * CC];     // NHWC fp16 leaky output
__device__ __half g_wdcH[9 * 64 * 64];               // [tap][oc][c], fp16
__device__ __half g_wcH[9 * 64 * 64];                // [tap][oc][c], fp16
__device__ __half g_womH[9 * 32 * 64];               // [tap][oc(27 pad32)][c], fp16

// ---------------------------------------------------------------------------
__device__ __forceinline__ void mma16(float4& d, const uint32_t* a, const uint32_t* bf) {
    asm volatile(
        "mma.sync.aligned.m16n8k16.row.col.f32.f16.f16.f32 "
        "{%0,%1,%2,%3},{%4,%5,%6,%7},{%8,%9},{%0,%1,%2,%3};\n"
        : "+f"(d.x), "+f"(d.y), "+f"(d.z), "+f"(d.w)
        : "r"(a[0]), "r"(a[1]), "r"(a[2]), "r"(a[3]), "r"(bf[0]), "r"(bf[1]));
}

__device__ __forceinline__ uint32_t smem_u32(const void* p) {
    return (uint32_t)__cvta_generic_to_shared(p);
}

__device__ __forceinline__ void ldsm_x4(uint32_t* r, uint32_t addr) {
    asm volatile("ldmatrix.sync.aligned.m8n8.x4.shared.b16 {%0,%1,%2,%3}, [%4];\n"
        : "=r"(r[0]), "=r"(r[1]), "=r"(r[2]), "=r"(r[3]) : "r"(addr));
}

// ---------------------------------------------------------------------------
// Kernel W: weights -> [tap][oc][c] fp16 (dc, c, om)
// ---------------------------------------------------------------------------
__global__ __launch_bounds__(256) void wtrans_kernel(const float* __restrict__ w_dc,
                                                     const float* __restrict__ w_c,
                                                     const float* __restrict__ w_om) {
    int i = blockIdx.x * 256 + threadIdx.x;
    if (i < 36864) {
        int tap = i >> 12, rem = i & 4095, o = rem >> 6, c = rem & 63;
        g_wdcH[i] = __float2half(w_dc[o * 576 + c * 9 + tap]);
    } else if (i < 73728) {
        int j = i - 36864;
        int tap = j >> 12, rem = j & 4095, o = rem >> 6, c = rem & 63;
        g_wcH[j] = __float2half(w_c[o * 576 + c * 9 + tap]);
    } else if (i < 92160) {
        int j = i - 73728;
        int tap = j >> 11, rem = j & 2047, o = rem >> 6, c = rem & 63;
        g_womH[j] = (o < 27) ? __float2half(w_om[o * 576 + c * 9 + tap])
                             : __float2half(0.f);
    }
}

// ---------------------------------------------------------------------------
// Kernel T: NCHW fp32 -> NHWC fp16
// ---------------------------------------------------------------------------
__global__ __launch_bounds__(256) void transpose_kernel(const float* __restrict__ x) {
    __shared__ float t[64 * 65];
    int tid = threadIdx.x;
    int blk = blockIdx.x;
    int b  = blk >> 8;
    int p0 = (blk & 255) * 64;

    #pragma unroll
    for (int i = tid; i < 4096; i += 256) {
        int c  = i >> 6;
        int pl = i & 63;
        t[pl * 65 + c] = x[((size_t)b * CC + c) * HWs + p0 + pl];
    }
    __syncthreads();
    #pragma unroll
    for (int i = tid; i < 2048; i += 256) {
        int pl = i >> 5;
        int cp = i & 31;
        __half2 v = __floats2half2_rn(t[pl * 65 + 2 * cp], t[pl * 65 + 2 * cp + 1]);
        *(__half2*)(g_xh + ((size_t)b * HWs + p0 + pl) * CC + 2 * cp) = v;
    }
}

// ---------------------------------------------------------------------------
// Kernel A: offsets+mask conv, fp16 m16n8k16 on NHWC fp16 x (conv2 skeleton).
// 128-px row blocks, one sync/tap pipeline. N=32 (27 used).
// sval [2][136px][72h], swk [2][32oc][72h]. Warp tile 32px x 16oc.
// Epilogue: bias, 2*sigmoid(mask), interleaved [px][27] store.
// ---------------------------------------------------------------------------
#define OM_SMEM_BYTES ((2*136*72 + 2*32*72) * 2)
__global__ __launch_bounds__(256, 4) void offmask_h(const float* __restrict__ b_om) {
    extern __shared__ __half smh[];
    __half* sval = smh;                  // [2][136][72]
    __half* swk  = smh + 2 * 136 * 72;   // [2][32][72]

    int tid = threadIdx.x;
    int b = blockIdx.x >> 7;
    int h = blockIdx.x & 127;

    int lane = tid & 31, wid = tid >> 5;
    int warp_m = wid & 3;                // 4 x 32 px
    int warp_n = wid >> 2;               // 2 x 16 oc
    int lq = lane >> 2, lr = lane & 3;

    float4 acc[2][2];
    #pragma unroll
    for (int mt = 0; mt < 2; ++mt)
        #pragma unroll
        for (int nt = 0; nt < 2; ++nt) acc[mt][nt] = make_float4(0.f, 0.f, 0.f, 0.f);

    const __half* xb = g_xh + (size_t)b * HWs * CC;

    // row stager: sval[buf][j][c] = x[y][j-1][c], j in 0..129
    auto stage_row = [&](int y, __half* dstv) {
        bool yok = (y >= 0) & (y < HH);
        #pragma unroll
        for (int r = 0; r < 5; ++r) {
            int i = tid + 256 * r;
            if (i < 1040) {
                int jj = i >> 3, o = i & 7;
                int xg = jj - 1;
                uint4 v = make_uint4(0u, 0u, 0u, 0u);
                if (yok && xg >= 0 && xg < WW)
                    v = __ldg((const uint4*)(xb + ((size_t)y * WW + xg) * CC + o * 8));
                *(uint4*)&dstv[jj * 72 + o * 8] = v;
            }
        }
    };

    // prologue: row dy=0 into buf0, tap0 weights into wbuf0 (256 uint4)
    stage_row(h - 1, sval);
    {
        int idx = tid;
        ((uint4*)swk)[(idx >> 3) * 9 + (idx & 7)] = ((const uint4*)g_womH)[idx];
    }
    __syncthreads();

    #pragma unroll 1
    for (int t = 0; t < KK; ++t) {
        int dy = t / 3, dx = t % 3;
        int wcur = t & 1, wnxt = wcur ^ 1;
        int abuf = dy & 1;
        bool pre = t < 8;

        const uint32_t* svw = (const uint32_t*)(sval + abuf * 136 * 72);
        const uint32_t* wbw = (const uint32_t*)(swk + wcur * 32 * 72);
        #pragma unroll
        for (int ks = 0; ks < 4; ++ks) {
            uint32_t a[2][4];
            #pragma unroll
            for (int mt = 0; mt < 2; ++mt) {
                int pxb = warp_m * 32 + mt * 16 + lq + dx;
                a[mt][0] = svw[pxb * 36 + ks * 8 + lr];
                a[mt][1] = svw[(pxb + 8) * 36 + ks * 8 + lr];
                a[mt][2] = svw[pxb * 36 + ks * 8 + lr + 4];
                a[mt][3] = svw[(pxb + 8) * 36 + ks * 8 + lr + 4];
            }
            uint32_t bw[2][2];
            #pragma unroll
            for (int nt = 0; nt < 2; ++nt) {
                int oc = warp_n * 16 + nt * 8 + lq;
                bw[nt][0] = wbw[oc * 36 + ks * 8 + lr];
                bw[nt][1] = wbw[oc * 36 + ks * 8 + lr + 4];
            }
            #pragma unroll
            for (int mt = 0; mt < 2; ++mt)
                #pragma unroll
                for (int nt = 0; nt < 2; ++nt)
                    mma16(acc[mt][nt], a[mt], bw[nt]);
        }

        if (dx == 0 && dy < 2)
            stage_row(h + dy, sval + (abuf ^ 1) * 136 * 72);
        if (pre) {
            int idx = tid;
            ((uint4*)(swk + wnxt * 32 * 72))[(idx >> 3) * 9 + (idx & 7)] =
                ((const uint4*)g_womH)[(t + 1) * 256 + idx];
        }
        __syncthreads();
    }

    // epilogue: transpose via smem (fp32), bias + 2*sigmoid(mask), store
    float* outs = (float*)smh;   // [32 oc][136 px] = 17.4KB, fits sval region
    #pragma unroll
    for (int mt = 0; mt < 2; ++mt) {
        #pragma unroll
        for (int nt = 0; nt < 2; ++nt) {
            int px = warp_m * 32 + mt * 16 + lq;
            int oc = warp_n * 16 + nt * 8 + 2 * lr;
            float4 v = acc[mt][nt];
            outs[oc * 136 + px]           = v.x;
            outs[(oc + 1) * 136 + px]     = v.y;
            outs[oc * 136 + px + 8]       = v.z;
            outs[(oc + 1) * 136 + px + 8] = v.w;
        }
    }
    __syncthreads();
    float* dst = g_offmask + ((size_t)b * HWs + h * WW) * 27;
    for (int idx = tid; idx < 128 * 27; idx += 256) {
        int px = idx / 27, e = idx - px * 27;
        int k = e / 3, r = e - 3 * k;
        int src = (r < 2) ? (2 * k + r) : (18 + k);
        float v = outs[src * 136 + px] + __ldg(b_om + src);
        if (r == 2) v = 2.f / (1.f + expf(-v));
        dst[px * 27 + e] = v;
    }
}

// ---------------------------------------------------------------------------
// deform gather (fp16, per-thread form): thread = (pixel pg, channel octet
// oct). One LDG.128 per corner, bilinear in fp32, one STS.128 out.
// ---------------------------------------------------------------------------
__device__ __forceinline__ void dgather32h(const __half* __restrict__ xb,
                                           const float* __restrict__ omrow,
                                           __half* __restrict__ dst,
                                           int h, int w0, int tap,
                                           int pg, int oct) {
    int ty = h - 1 + tap / 3;
    int txoff = tap % 3 - 1;
    const float* o3 = omrow + pg * 27 + tap * 3;
    float offy = __ldg(o3), offx = __ldg(o3 + 1), msk = __ldg(o3 + 2);
    float py = (float)ty + offy;
    float px = (float)(w0 + pg + txoff) + offx;
    float y0f = floorf(py), x0f = floorf(px);
    float ly = py - y0f, lx = px - x0f;
    int y0 = (int)y0f, x0 = (int)x0f;
    float wq[4] = {(1.f - ly) * (1.f - lx) * msk, (1.f - ly) * lx * msk,
                   ly * (1.f - lx) * msk,          ly * lx * msk};
    int ys[2] = {y0, y0 + 1};
    int xs[2] = {x0, x0 + 1};
    bool yok[2] = {(y0 >= 0) & (y0 < HH), (y0 + 1 >= 0) & (y0 + 1 < HH)};
    bool xok[2] = {(x0 >= 0) & (x0 < WW), (x0 + 1 >= 0) & (x0 + 1 < WW)};

    float u[8];
    #pragma unroll
    for (int j = 0; j < 8; ++j) u[j] = 0.f;

    #pragma unroll
    for (int sy = 0; sy < 2; ++sy) {
        #pragma unroll
        for (int sx = 0; sx < 2; ++sx) {
            if (yok[sy] && xok[sx]) {
                uint4 raw = __ldg((const uint4*)(xb +
                    ((size_t)(ys[sy] * WW + xs[sx])) * CC + oct * 8));
                float w = wq[sy * 2 + sx];
                const __half2* hp = (const __half2*)&raw;
                #pragma unroll
                for (int q = 0; q < 4; ++q) {
                    float2 f = __half22float2(hp[q]);
                    u[2 * q]     += w * f.x;
                    u[2 * q + 1] += w * f.y;
                }
            }
        }
    }
    __align__(16) __half2 p[4];
    #pragma unroll
    for (int q = 0; q < 4; ++q) p[q] = __floats2half2_rn(u[2 * q], u[2 * q + 1]);
    *(uint4*)&dst[pg * 72 + oct * 8] = *(const uint4*)p;
}

// ---------------------------------------------------------------------------
// Kernel B: modulated deformable conv 64->64, fp16 m16n8k16 tensor cores.
// 32-px tiles (4096 blocks), 4 blocks/SM. One sync/tap pipeline with
// ldmatrix.x4 fragment loads. Warp tile 16px x 16oc. (R13 version)
// ---------------------------------------------------------------------------
#define B_SMEM_BYTES ((2*32*72 + 2*64*72) * 2)
__global__ __launch_bounds__(256, 4) void deform_kernel(const float* __restrict__ b_dc) {
    extern __shared__ __half smh[];
    __half* sval = smh;                  // [2][32][72]
    __half* swk  = smh + 2 * 32 * 72;    // [2][64][72]

    int tid = threadIdx.x;
    int blk = blockIdx.x;
    int b = blk >> 9;
    int rem = blk & 511;
    int h = rem >> 2;
    int w0 = (rem & 3) * 32;

    int lane = tid & 31, wid = tid >> 5;
    int warp_m = wid & 1;                // 2 x 16 px
    int warp_n = wid >> 1;               // 4 x 16 oc
    int lq = lane >> 2, lr = lane & 3;

    int aRowL = warp_m * 16 + (lane & 7) + ((lane >> 3) & 1) * 8;
    int aColL = ((lane >> 4) & 1) * 8;
    int bRowL = warp_n * 16 + ((lane >> 4) & 1) * 8 + (lane & 7);
    int bColL = ((lane >> 3) & 1) * 8;

    int oct = tid & 7;                   // channel octet (8 ch)
    int pg  = tid >> 3;                  // pixel 0..31
    const __half* xb = g_xh + (size_t)b * HWs * CC;
    const float* omrow = g_offmask + ((size_t)b * HWs + h * WW + w0) * 27;

    float4 acc[2];
    acc[0] = make_float4(0.f, 0.f, 0.f, 0.f);
    acc[1] = make_float4(0.f, 0.f, 0.f, 0.f);

    // prologue: tap0 weights + gather
    #pragma unroll
    for (int r = 0; r < 2; ++r) {
        int idx = tid + 256 * r;
        ((uint4*)swk)[(idx >> 3) * 9 + (idx & 7)] = ((const uint4*)g_wdcH)[idx];
    }
    dgather32h(xb, omrow, sval, h, w0, 0, pg, oct);
    __syncthreads();

    #pragma unroll 1
    for (int tap = 0; tap < KK; ++tap) {
        int cur = tap & 1, nxt = cur ^ 1;
        bool pre = tap < 8;

        const __half* sv = sval + cur * 32 * 72;
        const __half* wb = swk + cur * 64 * 72;
        uint32_t aAddr = smem_u32(&sv[aRowL * 72 + aColL]);
        uint32_t bAddr = smem_u32(&wb[bRowL * 72 + bColL]);
        #pragma unroll
        for (int ks = 0; ks < 4; ++ks) {
            uint32_t a[4], bq[4];
            ldsm_x4(a, aAddr + ks * 32);
            ldsm_x4(bq, bAddr + ks * 32);
            mma16(acc[0], a, bq);
            mma16(acc[1], a, bq + 2);
        }

        if (pre) {
            #pragma unroll
            for (int r = 0; r < 2; ++r) {
                int idx = tid + 256 * r;
                ((uint4*)(swk + nxt * 64 * 72))[(idx >> 3) * 9 + (idx & 7)] =
                    ((const uint4*)g_wdcH)[(tap + 1) * 512 + idx];
            }
            dgather32h(xb, omrow, sval + nxt * 32 * 72, h, w0, tap + 1, pg, oct);
        }
        __syncthreads();
    }

    // epilogue: bias + LeakyReLU -> outs [32px][72oc] fp16, then NHWC store
    __half* outs = smh;
    {
        int px = warp_m * 16 + lq;
        #pragma unroll
        for (int nt = 0; nt < 2; ++nt) {
            int oc = warp_n * 16 + nt * 8 + 2 * lr;
            float b0 = __ldg(b_dc + oc), b1 = __ldg(b_dc + oc + 1);
            float4 v = acc[nt];
            float e0 = v.x + b0, e1 = v.y + b1, e2 = v.z + b0, e3 = v.w + b1;
            e0 = e0 > 0.f ? e0 : 0.2f * e0;
            e1 = e1 > 0.f ? e1 : 0.2f * e1;
            e2 = e2 > 0.f ? e2 : 0.2f * e2;
            e3 = e3 > 0.f ? e3 : 0.2f * e3;
            *(__half2*)&outs[px * 72 + oc]       = __floats2half2_rn(e0, e1);
            *(__half2*)&outs[(px + 8) * 72 + oc] = __floats2half2_rn(e2, e3);
        }
    }
    __syncthreads();
    {
        int p = tid >> 3, seg = tid & 7;
        uint4 v = *(const uint4*)&outs[p * 72 + seg * 8];
        *(uint4*)(g_acth + ((size_t)b * HWs + h * WW + w0 + p) * CC + seg * 8) = v;
    }
}

// ---------------------------------------------------------------------------
// Kernel C: 3x3 conv 64->64 on fp16 NHWC act, fp16 m16n8k16 tensor cores.
// 128-px row blocks, one sync/tap pipeline, bias + fp32 residual epilogue.
// (R8 version, proven)
// ---------------------------------------------------------------------------
#define C_SMEM_BYTES ((2*136*72 + 2*64*72) * 2)
__global__ __launch_bounds__(256, 3) void conv2_kernel(const float* __restrict__ x,
                                                       const float* __restrict__ b_c,
                                                       float* __restrict__ out) {
    extern __shared__ __half smh[];
    __half* sval = smh;                  // [2][136][72]
    __half* swk  = smh + 2 * 136 * 72;   // [2][64][72]

    int tid = threadIdx.x;
    int b = blockIdx.x >> 7;
    int h = blockIdx.x & 127;

    int lane = tid & 31, wid = tid >> 5;
    int warp_m = wid & 3;                // 4 x 32 px
    int warp_n = wid >> 2;               // 2 x 32 oc
    int lq = lane >> 2, lr = lane & 3;

    float4 acc[2][4];
    #pragma unroll
    for (int mt = 0; mt < 2; ++mt)
        #pragma unroll
        for (int nt = 0; nt < 4; ++nt) acc[mt][nt] = make_float4(0.f, 0.f, 0.f, 0.f);

    const __half* actb = g_acth + (size_t)b * HWs * CC;

    auto stage_row = [&](int y, __half* dstv) {
        bool yok = (y >= 0) & (y < HH);
        #pragma unroll
        for (int r = 0; r < 5; ++r) {
            int i = tid + 256 * r;
            if (i < 1040) {
                int jj = i >> 3, o = i & 7;
                int xg = jj - 1;
                uint4 v = make_uint4(0u, 0u, 0u, 0u);
                if (yok && xg >= 0 && xg < WW)
                    v = __ldg((const uint4*)(actb + ((size_t)y * WW + xg) * CC + o * 8));
                *(uint4*)&dstv[jj * 72 + o * 8] = v;
            }
        }
    };

    stage_row(h - 1, sval);
    #pragma unroll
    for (int r = 0; r < 2; ++r) {
        int idx = tid + 256 * r;
        ((uint4*)swk)[(idx >> 3) * 9 + (idx & 7)] = ((const uint4*)g_wcH)[idx];
    }
    __syncthreads();

    #pragma unroll 1
    for (int t = 0; t < KK; ++t) {
        int dy = t / 3, dx = t % 3;
        int wcur = t & 1, wnxt = wcur ^ 1;
        int abuf = dy & 1;
        bool pre = t < 8;

        const uint32_t* svw = (const uint32_t*)(sval + abuf * 136 * 72);
        const uint32_t* wbw = (const uint32_t*)(swk + wcur * 64 * 72);
        #pragma unroll
        for (int ks = 0; ks < 4; ++ks) {
            uint32_t a[2][4];
            #pragma unroll
            for (int mt = 0; mt < 2; ++mt) {
                int pxb = warp_m * 32 + mt * 16 + lq + dx;
                a[mt][0] = svw[pxb * 36 + ks * 8 + lr];
                a[mt][1] = svw[(pxb + 8) * 36 + ks * 8 + lr];
                a[mt][2] = svw[pxb * 36 + ks * 8 + lr + 4];
                a[mt][3] = svw[(pxb + 8) * 36 + ks * 8 + lr + 4];
            }
            uint32_t bw[4][2];
            #pragma unroll
            for (int nt = 0; nt < 4; ++nt) {
                int oc = warp_n * 32 + nt * 8 + lq;
                bw[nt][0] = wbw[oc * 36 + ks * 8 + lr];
                bw[nt][1] = wbw[oc * 36 + ks * 8 + lr + 4];
            }
            #pragma unroll
            for (int mt = 0; mt < 2; ++mt)
                #pragma unroll
                for (int nt = 0; nt < 4; ++nt)
                    mma16(acc[mt][nt], a[mt], bw[nt]);
        }

        if (dx == 0 && dy < 2)
            stage_row(h + dy, sval + (abuf ^ 1) * 136 * 72);
        if (pre) {
            #pragma unroll
            for (int r = 0; r < 2; ++r) {
                int idx = tid + 256 * r;
                ((uint4*)(swk + wnxt * 64 * 72))[(idx >> 3) * 9 + (idx & 7)] =
                    ((const uint4*)g_wcH)[(t + 1) * 512 + idx];
            }
        }
        __syncthreads();
    }

    float* outs = (float*)smh;
    #pragma unroll
    for (int mt = 0; mt < 2; ++mt) {
        #pragma unroll
        for (int nt = 0; nt < 4; ++nt) {
            int px = warp_m * 32 + mt * 16 + lq;
            int oc = warp_n * 32 + nt * 8 + 2 * lr;
            float b0 = __ldg(b_c + oc), b1 = __ldg(b_c + oc + 1);
            float4 v = acc[mt][nt];
            outs[oc * 136 + px]           = v.x + b0;
            outs[(oc + 1) * 136 + px]     = v.y + b1;
            outs[oc * 136 + px + 8]       = v.z + b0;
            outs[(oc + 1) * 136 + px + 8] = v.w + b1;
        }
    }
    __syncthreads();
    #pragma unroll
    for (int j2 = 0; j2 < 8; ++j2) {
        int idx = tid + 256 * j2;
        int oc = idx >> 5, pxq = idx & 31;
        size_t base = ((size_t)b * CC + oc) * HWs + h * WW + pxq * 4;
        float4 v = *(const float4*)&outs[oc * 136 + pxq * 4];
        float4 r = *(const float4*)(x + base);
        v.x += r.x; v.y += r.y; v.z += r.z; v.w += r.w;
        *(float4*)(out + base) = v;
    }
}

// ---------------------------------------------------------------------------
extern "C" void kernel_launch(void* const* d_in, const int* in_sizes, int n_in,
                              void* d_out, int out_size) {
    const float* x    = (const float*)d_in[0];
    const float* w_om = (const float*)d_in[1];
    const float* b_om = (const float*)d_in[2];
    const float* w_dc = (const float*)d_in[3];
    const float* b_dc = (const float*)d_in[4];
    const float* w_c  = (const float*)d_in[5];
    const float* b_c  = (const float*)d_in[6];
    float* out = (float*)d_out;

    cudaFuncSetAttribute(offmask_h, cudaFuncAttributeMaxDynamicSharedMemorySize,
                         OM_SMEM_BYTES);
    cudaFuncSetAttribute(deform_kernel, cudaFuncAttributeMaxDynamicSharedMemorySize,
                         B_SMEM_BYTES);
    cudaFuncSetAttribute(conv2_kernel, cudaFuncAttributeMaxDynamicSharedMemorySize,
                         C_SMEM_BYTES);

    wtrans_kernel<<<360, 256>>>(w_dc, w_c, w_om);
    transpose_kernel<<<BB * (HWs / 64), 256>>>(x);

    offmask_h<<<BB * HH, 256, OM_SMEM_BYTES>>>(b_om);

    deform_kernel<<<BB * HH * 4, 256, B_SMEM_BYTES>>>(b_dc);

    conv2_kernel<<<BB * HH, 256, C_SMEM_BYTES>>>(x, b_c, out);
}

// round 15
// speedup vs baseline: 1.2704x; 1.0289x over previous
#include <cuda_runtime.h>
#include <cuda_fp16.h>
#include <cstdint>
#include <math.h>

#define HH 128
#define WW 128
#define HWs (HH*WW)
#define CC 64
#define BB 8
#define KK 9
#define CK 576

// Scratch (device globals: allocation-free kernel_launch)
__device__ __half g_xh[(size_t)BB * HWs * CC];       // NHWC fp16 copy of x
__device__ float  g_offmask[(size_t)BB * HWs * 27];  // [b][pix][k][{offy,offx,mask}]
__device__ __half g_acth[(size_t)BB * HWs * CC];     // NHWC fp16 leaky output
__device__ __half g_wdcH[9 * 64 * 64];               // [tap][oc][c], fp16
__device__ __half g_wcH[9 * 64 * 64];                // [tap][oc][c], fp16
__device__ __half g_womH[9 * 32 * 64];               // [tap][oc(27 pad32)][c], fp16

// ---------------------------------------------------------------------------
__device__ __forceinline__ void mma16(float4& d, const uint32_t* a, const uint32_t* bf) {
    asm volatile(
        "mma.sync.aligned.m16n8k16.row.col.f32.f16.f16.f32 "
        "{%0,%1,%2,%3},{%4,%5,%6,%7},{%8,%9},{%0,%1,%2,%3};\n"
        : "+f"(d.x), "+f"(d.y), "+f"(d.z), "+f"(d.w)
        : "r"(a[0]), "r"(a[1]), "r"(a[2]), "r"(a[3]), "r"(bf[0]), "r"(bf[1]));
}

__device__ __forceinline__ uint32_t smem_u32(const void* p) {
    return (uint32_t)__cvta_generic_to_shared(p);
}

__device__ __forceinline__ void ldsm_x4(uint32_t* r, uint32_t addr) {
    asm volatile("ldmatrix.sync.aligned.m8n8.x4.shared.b16 {%0,%1,%2,%3}, [%4];\n"
        : "=r"(r[0]), "=r"(r[1]), "=r"(r[2]), "=r"(r[3]) : "r"(addr));
}

// ---------------------------------------------------------------------------
// Kernel W: weights -> [tap][oc][c] fp16 (dc, c, om)
// ---------------------------------------------------------------------------
__global__ __launch_bounds__(256) void wtrans_kernel(const float* __restrict__ w_dc,
                                                     const float* __restrict__ w_c,
                                                     const float* __restrict__ w_om) {
    int i = blockIdx.x * 256 + threadIdx.x;
    if (i < 36864) {
        int tap = i >> 12, rem = i & 4095, o = rem >> 6, c = rem & 63;
        g_wdcH[i] = __float2half(w_dc[o * 576 + c * 9 + tap]);
    } else if (i < 73728) {
        int j = i - 36864;
        int tap = j >> 12, rem = j & 4095, o = rem >> 6, c = rem & 63;
        g_wcH[j] = __float2half(w_c[o * 576 + c * 9 + tap]);
    } else if (i < 92160) {
        int j = i - 73728;
        int tap = j >> 11, rem = j & 2047, o = rem >> 6, c = rem & 63;
        g_womH[j] = (o < 27) ? __float2half(w_om[o * 576 + c * 9 + tap])
                             : __float2half(0.f);
    }
}

// ---------------------------------------------------------------------------
// Kernel T: NCHW fp32 -> NHWC fp16
// ---------------------------------------------------------------------------
__global__ __launch_bounds__(256) void transpose_kernel(const float* __restrict__ x) {
    __shared__ float t[64 * 65];
    int tid = threadIdx.x;
    int blk = blockIdx.x;
    int b  = blk >> 8;
    int p0 = (blk & 255) * 64;

    #pragma unroll
    for (int i = tid; i < 4096; i += 256) {
        int c  = i >> 6;
        int pl = i & 63;
        t[pl * 65 + c] = x[((size_t)b * CC + c) * HWs + p0 + pl];
    }
    __syncthreads();
    #pragma unroll
    for (int i = tid; i < 2048; i += 256) {
        int pl = i >> 5;
        int cp = i & 31;
        __half2 v = __floats2half2_rn(t[pl * 65 + 2 * cp], t[pl * 65 + 2 * cp + 1]);
        *(__half2*)(g_xh + ((size_t)b * HWs + p0 + pl) * CC + 2 * cp) = v;
    }
}

// ---------------------------------------------------------------------------
// Kernel A: offsets+mask conv, fp16 m16n8k16 on NHWC fp16 x (R13, proven).
// ---------------------------------------------------------------------------
#define OM_SMEM_BYTES ((2*136*72 + 2*32*72) * 2)
__global__ __launch_bounds__(256, 4) void offmask_h(const float* __restrict__ b_om) {
    extern __shared__ __half smh[];
    __half* sval = smh;                  // [2][136][72]
    __half* swk  = smh + 2 * 136 * 72;   // [2][32][72]

    int tid = threadIdx.x;
    int b = blockIdx.x >> 7;
    int h = blockIdx.x & 127;

    int lane = tid & 31, wid = tid >> 5;
    int warp_m = wid & 3;                // 4 x 32 px
    int warp_n = wid >> 2;               // 2 x 16 oc
    int lq = lane >> 2, lr = lane & 3;

    float4 acc[2][2];
    #pragma unroll
    for (int mt = 0; mt < 2; ++mt)
        #pragma unroll
        for (int nt = 0; nt < 2; ++nt) acc[mt][nt] = make_float4(0.f, 0.f, 0.f, 0.f);

    const __half* xb = g_xh + (size_t)b * HWs * CC;

    auto stage_row = [&](int y, __half* dstv) {
        bool yok = (y >= 0) & (y < HH);
        #pragma unroll
        for (int r = 0; r < 5; ++r) {
            int i = tid + 256 * r;
            if (i < 1040) {
                int jj = i >> 3, o = i & 7;
                int xg = jj - 1;
                uint4 v = make_uint4(0u, 0u, 0u, 0u);
                if (yok && xg >= 0 && xg < WW)
                    v = __ldg((const uint4*)(xb + ((size_t)y * WW + xg) * CC + o * 8));
                *(uint4*)&dstv[jj * 72 + o * 8] = v;
            }
        }
    };

    stage_row(h - 1, sval);
    {
        int idx = tid;
        ((uint4*)swk)[(idx >> 3) * 9 + (idx & 7)] = ((const uint4*)g_womH)[idx];
    }
    __syncthreads();

    #pragma unroll 1
    for (int t = 0; t < KK; ++t) {
        int dy = t / 3, dx = t % 3;
        int wcur = t & 1, wnxt = wcur ^ 1;
        int abuf = dy & 1;
        bool pre = t < 8;

        const uint32_t* svw = (const uint32_t*)(sval + abuf * 136 * 72);
        const uint32_t* wbw = (const uint32_t*)(swk + wcur * 32 * 72);
        #pragma unroll
        for (int ks = 0; ks < 4; ++ks) {
            uint32_t a[2][4];
            #pragma unroll
            for (int mt = 0; mt < 2; ++mt) {
                int pxb = warp_m * 32 + mt * 16 + lq + dx;
                a[mt][0] = svw[pxb * 36 + ks * 8 + lr];
                a[mt][1] = svw[(pxb + 8) * 36 + ks * 8 + lr];
                a[mt][2] = svw[pxb * 36 + ks * 8 + lr + 4];
                a[mt][3] = svw[(pxb + 8) * 36 + ks * 8 + lr + 4];
            }
            uint32_t bw[2][2];
            #pragma unroll
            for (int nt = 0; nt < 2; ++nt) {
                int oc = warp_n * 16 + nt * 8 + lq;
                bw[nt][0] = wbw[oc * 36 + ks * 8 + lr];
                bw[nt][1] = wbw[oc * 36 + ks * 8 + lr + 4];
            }
            #pragma unroll
            for (int mt = 0; mt < 2; ++mt)
                #pragma unroll
                for (int nt = 0; nt < 2; ++nt)
                    mma16(acc[mt][nt], a[mt], bw[nt]);
        }

        if (dx == 0 && dy < 2)
            stage_row(h + dy, sval + (abuf ^ 1) * 136 * 72);
        if (pre) {
            int idx = tid;
            ((uint4*)(swk + wnxt * 32 * 72))[(idx >> 3) * 9 + (idx & 7)] =
                ((const uint4*)g_womH)[(t + 1) * 256 + idx];
        }
        __syncthreads();
    }

    float* outs = (float*)smh;   // [32 oc][136 px]
    #pragma unroll
    for (int mt = 0; mt < 2; ++mt) {
        #pragma unroll
        for (int nt = 0; nt < 2; ++nt) {
            int px = warp_m * 32 + mt * 16 + lq;
            int oc = warp_n * 16 + nt * 8 + 2 * lr;
            float4 v = acc[mt][nt];
            outs[oc * 136 + px]           = v.x;
            outs[(oc + 1) * 136 + px]     = v.y;
            outs[oc * 136 + px + 8]       = v.z;
            outs[(oc + 1) * 136 + px + 8] = v.w;
        }
    }
    __syncthreads();
    float* dst = g_offmask + ((size_t)b * HWs + h * WW) * 27;
    for (int idx = tid; idx < 128 * 27; idx += 256) {
        int px = idx / 27, e = idx - px * 27;
        int k = e / 3, r = e - 3 * k;
        int src = (r < 2) ? (2 * k + r) : (18 + k);
        float v = outs[src * 136 + px] + __ldg(b_om + src);
        if (r == 2) v = 2.f / (1.f + expf(-v));
        dst[px * 27 + e] = v;
    }
}

// ---------------------------------------------------------------------------
// deform gather (fp16, per-thread form)
// ---------------------------------------------------------------------------
__device__ __forceinline__ void dgather32h(const __half* __restrict__ xb,
                                           const float* __restrict__ omrow,
                                           __half* __restrict__ dst,
                                           int h, int w0, int tap,
                                           int pg, int oct) {
    int ty = h - 1 + tap / 3;
    int txoff = tap % 3 - 1;
    const float* o3 = omrow + pg * 27 + tap * 3;
    float offy = __ldg(o3), offx = __ldg(o3 + 1), msk = __ldg(o3 + 2);
    float py = (float)ty + offy;
    float px = (float)(w0 + pg + txoff) + offx;
    float y0f = floorf(py), x0f = floorf(px);
    float ly = py - y0f, lx = px - x0f;
    int y0 = (int)y0f, x0 = (int)x0f;
    float wq[4] = {(1.f - ly) * (1.f - lx) * msk, (1.f - ly) * lx * msk,
                   ly * (1.f - lx) * msk,          ly * lx * msk};
    int ys[2] = {y0, y0 + 1};
    int xs[2] = {x0, x0 + 1};
    bool yok[2] = {(y0 >= 0) & (y0 < HH), (y0 + 1 >= 0) & (y0 + 1 < HH)};
    bool xok[2] = {(x0 >= 0) & (x0 < WW), (x0 + 1 >= 0) & (x0 + 1 < WW)};

    float u[8];
    #pragma unroll
    for (int j = 0; j < 8; ++j) u[j] = 0.f;

    #pragma unroll
    for (int sy = 0; sy < 2; ++sy) {
        #pragma unroll
        for (int sx = 0; sx < 2; ++sx) {
            if (yok[sy] && xok[sx]) {
                uint4 raw = __ldg((const uint4*)(xb +
                    ((size_t)(ys[sy] * WW + xs[sx])) * CC + oct * 8));
                float w = wq[sy * 2 + sx];
                const __half2* hp = (const __half2*)&raw;
                #pragma unroll
                for (int q = 0; q < 4; ++q) {
                    float2 f = __half22float2(hp[q]);
                    u[2 * q]     += w * f.x;
                    u[2 * q + 1] += w * f.y;
                }
            }
        }
    }
    __align__(16) __half2 p[4];
    #pragma unroll
    for (int q = 0; q < 4; ++q) p[q] = __floats2half2_rn(u[2 * q], u[2 * q + 1]);
    *(uint4*)&dst[pg * 72 + oct * 8] = *(const uint4*)p;
}

// ---------------------------------------------------------------------------
// Kernel B: modulated deformable conv 64->64, fp16 m16n8k16 + ldmatrix.
// 32-px tiles (4096 blocks). NOW 5 blocks/SM (reg-capped at 51).
// ---------------------------------------------------------------------------
#define B_SMEM_BYTES ((2*32*72 + 2*64*72) * 2)
__global__ __launch_bounds__(256, 5) void deform_kernel(const float* __restrict__ b_dc) {
    extern __shared__ __half smh[];
    __half* sval = smh;                  // [2][32][72]
    __half* swk  = smh + 2 * 32 * 72;    // [2][64][72]

    int tid = threadIdx.x;
    int blk = blockIdx.x;
    int b = blk >> 9;
    int rem = blk & 511;
    int h = rem >> 2;
    int w0 = (rem & 3) * 32;

    int lane = tid & 31, wid = tid >> 5;
    int warp_m = wid & 1;                // 2 x 16 px
    int warp_n = wid >> 1;               // 4 x 16 oc
    int lq = lane >> 2, lr = lane & 3;

    int aRowL = warp_m * 16 + (lane & 7) + ((lane >> 3) & 1) * 8;
    int aColL = ((lane >> 4) & 1) * 8;
    int bRowL = warp_n * 16 + ((lane >> 4) & 1) * 8 + (lane & 7);
    int bColL = ((lane >> 3) & 1) * 8;

    int oct = tid & 7;
    int pg  = tid >> 3;
    const __half* xb = g_xh + (size_t)b * HWs * CC;
    const float* omrow = g_offmask + ((size_t)b * HWs + h * WW + w0) * 27;

    float4 acc[2];
    acc[0] = make_float4(0.f, 0.f, 0.f, 0.f);
    acc[1] = make_float4(0.f, 0.f, 0.f, 0.f);

    #pragma unroll
    for (int r = 0; r < 2; ++r) {
        int idx = tid + 256 * r;
        ((uint4*)swk)[(idx >> 3) * 9 + (idx & 7)] = ((const uint4*)g_wdcH)[idx];
    }
    dgather32h(xb, omrow, sval, h, w0, 0, pg, oct);
    __syncthreads();

    #pragma unroll 1
    for (int tap = 0; tap < KK; ++tap) {
        int cur = tap & 1, nxt = cur ^ 1;
        bool pre = tap < 8;

        const __half* sv = sval + cur * 32 * 72;
        const __half* wb = swk + cur * 64 * 72;
        uint32_t aAddr = smem_u32(&sv[aRowL * 72 + aColL]);
        uint32_t bAddr = smem_u32(&wb[bRowL * 72 + bColL]);
        #pragma unroll
        for (int ks = 0; ks < 4; ++ks) {
            uint32_t a[4], bq[4];
            ldsm_x4(a, aAddr + ks * 32);
            ldsm_x4(bq, bAddr + ks * 32);
            mma16(acc[0], a, bq);
            mma16(acc[1], a, bq + 2);
        }

        if (pre) {
            #pragma unroll
            for (int r = 0; r < 2; ++r) {
                int idx = tid + 256 * r;
                ((uint4*)(swk + nxt * 64 * 72))[(idx >> 3) * 9 + (idx & 7)] =
                    ((const uint4*)g_wdcH)[(tap + 1) * 512 + idx];
            }
            dgather32h(xb, omrow, sval + nxt * 32 * 72, h, w0, tap + 1, pg, oct);
        }
        __syncthreads();
    }

    // epilogue
    __half* outs = smh;
    {
        int px = warp_m * 16 + lq;
        #pragma unroll
        for (int nt = 0; nt < 2; ++nt) {
            int oc = warp_n * 16 + nt * 8 + 2 * lr;
            float b0 = __ldg(b_dc + oc), b1 = __ldg(b_dc + oc + 1);
            float4 v = acc[nt];
            float e0 = v.x + b0, e1 = v.y + b1, e2 = v.z + b0, e3 = v.w + b1;
            e0 = e0 > 0.f ? e0 : 0.2f * e0;
            e1 = e1 > 0.f ? e1 : 0.2f * e1;
            e2 = e2 > 0.f ? e2 : 0.2f * e2;
            e3 = e3 > 0.f ? e3 : 0.2f * e3;
            *(__half2*)&outs[px * 72 + oc]       = __floats2half2_rn(e0, e1);
            *(__half2*)&outs[(px + 8) * 72 + oc] = __floats2half2_rn(e2, e3);
        }
    }
    __syncthreads();
    {
        int p = tid >> 3, seg = tid & 7;
        uint4 v = *(const uint4*)&outs[p * 72 + seg * 8];
        *(uint4*)(g_acth + ((size_t)b * HWs + h * WW + w0 + p) * CC + seg * 8) = v;
    }
}

// ---------------------------------------------------------------------------
// Kernel C: 3x3 conv 64->64 on fp16 NHWC act. sval rows 136->132 to fit
// 4 blocks/SM (smem 55.1KB); launch_bounds(256,4).
// ---------------------------------------------------------------------------
#define C_ROWS 132
#define C_SMEM_BYTES ((2*C_ROWS*72 + 2*64*72) * 2)
__global__ __launch_bounds__(256, 4) void conv2_kernel(const float* __restrict__ x,
                                                       const float* __restrict__ b_c,
                                                       float* __restrict__ out) {
    extern __shared__ __half smh[];
    __half* sval = smh;                  // [2][C_ROWS][72]
    __half* swk  = smh + 2 * C_ROWS * 72; // [2][64][72]

    int tid = threadIdx.x;
    int b = blockIdx.x >> 7;
    int h = blockIdx.x & 127;

    int lane = tid & 31, wid = tid >> 5;
    int warp_m = wid & 3;                // 4 x 32 px
    int warp_n = wid >> 2;               // 2 x 32 oc
    int lq = lane >> 2, lr = lane & 3;

    float4 acc[2][4];
    #pragma unroll
    for (int mt = 0; mt < 2; ++mt)
        #pragma unroll
        for (int nt = 0; nt < 4; ++nt) acc[mt][nt] = make_float4(0.f, 0.f, 0.f, 0.f);

    const __half* actb = g_acth + (size_t)b * HWs * CC;

    auto stage_row = [&](int y, __half* dstv) {
        bool yok = (y >= 0) & (y < HH);
        #pragma unroll
        for (int r = 0; r < 5; ++r) {
            int i = tid + 256 * r;
            if (i < 1040) {
                int jj = i >> 3, o = i & 7;
                int xg = jj - 1;
                uint4 v = make_uint4(0u, 0u, 0u, 0u);
                if (yok && xg >= 0 && xg < WW)
                    v = __ldg((const uint4*)(actb + ((size_t)y * WW + xg) * CC + o * 8));
                *(uint4*)&dstv[jj * 72 + o * 8] = v;
            }
        }
    };

    stage_row(h - 1, sval);
    #pragma unroll
    for (int r = 0; r < 2; ++r) {
        int idx = tid + 256 * r;
        ((uint4*)swk)[(idx >> 3) * 9 + (idx & 7)] = ((const uint4*)g_wcH)[idx];
    }
    __syncthreads();

    #pragma unroll 1
    for (int t = 0; t < KK; ++t) {
        int dy = t / 3, dx = t % 3;
        int wcur = t & 1, wnxt = wcur ^ 1;
        int abuf = dy & 1;
        bool pre = t < 8;

        const uint32_t* svw = (const uint32_t*)(sval + abuf * C_ROWS * 72);
        const uint32_t* wbw = (const uint32_t*)(swk + wcur * 64 * 72);
        #pragma unroll
        for (int ks = 0; ks < 4; ++ks) {
            uint32_t a[2][4];
            #pragma unroll
            for (int mt = 0; mt < 2; ++mt) {
                int pxb = warp_m * 32 + mt * 16 + lq + dx;
                a[mt][0] = svw[pxb * 36 + ks * 8 + lr];
                a[mt][1] = svw[(pxb + 8) * 36 + ks * 8 + lr];
                a[mt][2] = svw[pxb * 36 + ks * 8 + lr + 4];
                a[mt][3] = svw[(pxb + 8) * 36 + ks * 8 + lr + 4];
            }
            uint32_t bw[4][2];
            #pragma unroll
            for (int nt = 0; nt < 4; ++nt) {
                int oc = warp_n * 32 + nt * 8 + lq;
                bw[nt][0] = wbw[oc * 36 + ks * 8 + lr];
                bw[nt][1] = wbw[oc * 36 + ks * 8 + lr + 4];
            }
            #pragma unroll
            for (int mt = 0; mt < 2; ++mt)
                #pragma unroll
                for (int nt = 0; nt < 4; ++nt)
                    mma16(acc[mt][nt], a[mt], bw[nt]);
        }

        if (dx == 0 && dy < 2)
            stage_row(h + dy, sval + (abuf ^ 1) * C_ROWS * 72);
        if (pre) {
            #pragma unroll
            for (int r = 0; r < 2; ++r) {
                int idx = tid + 256 * r;
                ((uint4*)(swk + wnxt * 64 * 72))[(idx >> 3) * 9 + (idx & 7)] =
                    ((const uint4*)g_wcH)[(t + 1) * 512 + idx];
            }
        }
        __syncthreads();
    }

    float* outs = (float*)smh;   // [64 oc][136 px] = 34.8KB <= 55.1KB
    #pragma unroll
    for (int mt = 0; mt < 2; ++mt) {
        #pragma unroll
        for (int nt = 0; nt < 4; ++nt) {
            int px = warp_m * 32 + mt * 16 + lq;
            int oc = warp_n * 32 + nt * 8 + 2 * lr;
            float b0 = __ldg(b_c + oc), b1 = __ldg(b_c + oc + 1);
            float4 v = acc[mt][nt];
            outs[oc * 136 + px]           = v.x + b0;
            outs[(oc + 1) * 136 + px]     = v.y + b1;
            outs[oc * 136 + px + 8]       = v.z + b0;
            outs[(oc + 1) * 136 + px + 8] = v.w + b1;
        }
    }
    __syncthreads();
    #pragma unroll
    for (int j2 = 0; j2 < 8; ++j2) {
        int idx = tid + 256 * j2;
        int oc = idx >> 5, pxq = idx & 31;
        size_t base = ((size_t)b * CC + oc) * HWs + h * WW + pxq * 4;
        float4 v = *(const float4*)&outs[oc * 136 + pxq * 4];
        float4 r = *(const float4*)(x + base);
        v.x += r.x; v.y += r.y; v.z += r.z; v.w += r.w;
        *(float4*)(out + base) = v;
    }
}

// ---------------------------------------------------------------------------
extern "C" void kernel_launch(void* const* d_in, const int* in_sizes, int n_in,
                              void* d_out, int out_size) {
    const float* x    = (const float*)d_in[0];
    const float* w_om = (const float*)d_in[1];
    const float* b_om = (const float*)d_in[2];
    const float* w_dc = (const float*)d_in[3];
    const float* b_dc = (const float*)d_in[4];
    const float* w_c  = (const float*)d_in[5];
    const float* b_c  = (const float*)d_in[6];
    float* out = (float*)d_out;

    cudaFuncSetAttribute(offmask_h, cudaFuncAttributeMaxDynamicSharedMemorySize,
                         OM_SMEM_BYTES);
    cudaFuncSetAttribute(deform_kernel, cudaFuncAttributeMaxDynamicSharedMemorySize,
                         B_SMEM_BYTES);
    cudaFuncSetAttribute(conv2_kernel, cudaFuncAttributeMaxDynamicSharedMemorySize,
                         C_SMEM_BYTES);

    wtrans_kernel<<<360, 256>>>(w_dc, w_c, w_om);
    transpose_kernel<<<BB * (HWs / 64), 256>>>(x);

    offmask_h<<<BB * HH, 256, OM_SMEM_BYTES>>>(b_om);

    deform_kernel<<<BB * HH * 4, 256, B_SMEM_BYTES>>>(b_dc);

    conv2_kernel<<<BB * HH, 256, C_SMEM_BYTES>>>(x, b_c, out);
}

// round 16
// speedup vs baseline: 1.3053x; 1.0274x over previous
#include <cuda_runtime.h>
#include <cuda_fp16.h>
#include <cstdint>
#include <math.h>

#define HH 128
#define WW 128
#define HWs (HH*WW)
#define CC 64
#define BB 8
#define KK 9
#define CK 576

// Scratch (device globals: allocation-free kernel_launch)
__device__ __half g_xh[(size_t)BB * HWs * CC];       // NHWC fp16 copy of x
__device__ float  g_offmask[(size_t)BB * HWs * 27];  // [b][pix][k][{offy,offx,mask}]
__device__ __half g_acth[(size_t)BB * HWs * CC];     // NHWC fp16 leaky output
__device__ __half g_wdcH[9 * 64 * 64];               // [tap][oc][c], fp16
__device__ __half g_wcH[9 * 64 * 64];                // [tap][oc][c], fp16
__device__ __half g_womH[9 * 32 * 64];               // [tap][oc(27 pad32)][c], fp16

// ---------------------------------------------------------------------------
__device__ __forceinline__ void mma16(float4& d, const uint32_t* a, const uint32_t* bf) {
    asm volatile(
        "mma.sync.aligned.m16n8k16.row.col.f32.f16.f16.f32 "
        "{%0,%1,%2,%3},{%4,%5,%6,%7},{%8,%9},{%0,%1,%2,%3};\n"
        : "+f"(d.x), "+f"(d.y), "+f"(d.z), "+f"(d.w)
        : "r"(a[0]), "r"(a[1]), "r"(a[2]), "r"(a[3]), "r"(bf[0]), "r"(bf[1]));
}

__device__ __forceinline__ uint32_t smem_u32(const void* p) {
    return (uint32_t)__cvta_generic_to_shared(p);
}

__device__ __forceinline__ void ldsm_x4(uint32_t* r, uint32_t addr) {
    asm volatile("ldmatrix.sync.aligned.m8n8.x4.shared.b16 {%0,%1,%2,%3}, [%4];\n"
        : "=r"(r[0]), "=r"(r[1]), "=r"(r[2]), "=r"(r[3]) : "r"(addr));
}

// ---------------------------------------------------------------------------
// Kernel W: weights -> [tap][oc][c] fp16 (dc, c, om)
// ---------------------------------------------------------------------------
__global__ __launch_bounds__(256) void wtrans_kernel(const float* __restrict__ w_dc,
                                                     const float* __restrict__ w_c,
                                                     const float* __restrict__ w_om) {
    int i = blockIdx.x * 256 + threadIdx.x;
    if (i < 36864) {
        int tap = i >> 12, rem = i & 4095, o = rem >> 6, c = rem & 63;
        g_wdcH[i] = __float2half(w_dc[o * 576 + c * 9 + tap]);
    } else if (i < 73728) {
        int j = i - 36864;
        int tap = j >> 12, rem = j & 4095, o = rem >> 6, c = rem & 63;
        g_wcH[j] = __float2half(w_c[o * 576 + c * 9 + tap]);
    } else if (i < 92160) {
        int j = i - 73728;
        int tap = j >> 11, rem = j & 2047, o = rem >> 6, c = rem & 63;
        g_womH[j] = (o < 27) ? __float2half(w_om[o * 576 + c * 9 + tap])
                             : __float2half(0.f);
    }
}

// ---------------------------------------------------------------------------
// Kernel T: NCHW fp32 -> NHWC fp16
// ---------------------------------------------------------------------------
__global__ __launch_bounds__(256) void transpose_kernel(const float* __restrict__ x) {
    __shared__ float t[64 * 65];
    int tid = threadIdx.x;
    int blk = blockIdx.x;
    int b  = blk >> 8;
    int p0 = (blk & 255) * 64;

    #pragma unroll
    for (int i = tid; i < 4096; i += 256) {
        int c  = i >> 6;
        int pl = i & 63;
        t[pl * 65 + c] = x[((size_t)b * CC + c) * HWs + p0 + pl];
    }
    __syncthreads();
    #pragma unroll
    for (int i = tid; i < 2048; i += 256) {
        int pl = i >> 5;
        int cp = i & 31;
        __half2 v = __floats2half2_rn(t[pl * 65 + 2 * cp], t[pl * 65 + 2 * cp + 1]);
        *(__half2*)(g_xh + ((size_t)b * HWs + p0 + pl) * CC + 2 * cp) = v;
    }
}

// ---------------------------------------------------------------------------
// Kernel A: offsets+mask conv, fp16 m16n8k16 on NHWC fp16 x (R13, proven).
// ---------------------------------------------------------------------------
#define OM_SMEM_BYTES ((2*136*72 + 2*32*72) * 2)
__global__ __launch_bounds__(256, 4) void offmask_h(const float* __restrict__ b_om) {
    extern __shared__ __half smh[];
    __half* sval = smh;                  // [2][136][72]
    __half* swk  = smh + 2 * 136 * 72;   // [2][32][72]

    int tid = threadIdx.x;
    int b = blockIdx.x >> 7;
    int h = blockIdx.x & 127;

    int lane = tid & 31, wid = tid >> 5;
    int warp_m = wid & 3;                // 4 x 32 px
    int warp_n = wid >> 2;               // 2 x 16 oc
    int lq = lane >> 2, lr = lane & 3;

    float4 acc[2][2];
    #pragma unroll
    for (int mt = 0; mt < 2; ++mt)
        #pragma unroll
        for (int nt = 0; nt < 2; ++nt) acc[mt][nt] = make_float4(0.f, 0.f, 0.f, 0.f);

    const __half* xb = g_xh + (size_t)b * HWs * CC;

    auto stage_row = [&](int y, __half* dstv) {
        bool yok = (y >= 0) & (y < HH);
        #pragma unroll
        for (int r = 0; r < 5; ++r) {
            int i = tid + 256 * r;
            if (i < 1040) {
                int jj = i >> 3, o = i & 7;
                int xg = jj - 1;
                uint4 v = make_uint4(0u, 0u, 0u, 0u);
                if (yok && xg >= 0 && xg < WW)
                    v = __ldg((const uint4*)(xb + ((size_t)y * WW + xg) * CC + o * 8));
                *(uint4*)&dstv[jj * 72 + o * 8] = v;
            }
        }
    };

    stage_row(h - 1, sval);
    {
        int idx = tid;
        ((uint4*)swk)[(idx >> 3) * 9 + (idx & 7)] = ((const uint4*)g_womH)[idx];
    }
    __syncthreads();

    #pragma unroll 1
    for (int t = 0; t < KK; ++t) {
        int dy = t / 3, dx = t % 3;
        int wcur = t & 1, wnxt = wcur ^ 1;
        int abuf = dy & 1;
        bool pre = t < 8;

        const uint32_t* svw = (const uint32_t*)(sval + abuf * 136 * 72);
        const uint32_t* wbw = (const uint32_t*)(swk + wcur * 32 * 72);
        #pragma unroll
        for (int ks = 0; ks < 4; ++ks) {
            uint32_t a[2][4];
            #pragma unroll
            for (int mt = 0; mt < 2; ++mt) {
                int pxb = warp_m * 32 + mt * 16 + lq + dx;
                a[mt][0] = svw[pxb * 36 + ks * 8 + lr];
                a[mt][1] = svw[(pxb + 8) * 36 + ks * 8 + lr];
                a[mt][2] = svw[pxb * 36 + ks * 8 + lr + 4];
                a[mt][3] = svw[(pxb + 8) * 36 + ks * 8 + lr + 4];
            }
            uint32_t bw[2][2];
            #pragma unroll
            for (int nt = 0; nt < 2; ++nt) {
                int oc = warp_n * 16 + nt * 8 + lq;
                bw[nt][0] = wbw[oc * 36 + ks * 8 + lr];
                bw[nt][1] = wbw[oc * 36 + ks * 8 + lr + 4];
            }
            #pragma unroll
            for (int mt = 0; mt < 2; ++mt)
                #pragma unroll
                for (int nt = 0; nt < 2; ++nt)
                    mma16(acc[mt][nt], a[mt], bw[nt]);
        }

        if (dx == 0 && dy < 2)
            stage_row(h + dy, sval + (abuf ^ 1) * 136 * 72);
        if (pre) {
            int idx = tid;
            ((uint4*)(swk + wnxt * 32 * 72))[(idx >> 3) * 9 + (idx & 7)] =
                ((const uint4*)g_womH)[(t + 1) * 256 + idx];
        }
        __syncthreads();
    }

    float* outs = (float*)smh;   // [32 oc][136 px]
    #pragma unroll
    for (int mt = 0; mt < 2; ++mt) {
        #pragma unroll
        for (int nt = 0; nt < 2; ++nt) {
            int px = warp_m * 32 + mt * 16 + lq;
            int oc = warp_n * 16 + nt * 8 + 2 * lr;
            float4 v = acc[mt][nt];
            outs[oc * 136 + px]           = v.x;
            outs[(oc + 1) * 136 + px]     = v.y;
            outs[oc * 136 + px + 8]       = v.z;
            outs[(oc + 1) * 136 + px + 8] = v.w;
        }
    }
    __syncthreads();
    float* dst = g_offmask + ((size_t)b * HWs + h * WW) * 27;
    for (int idx = tid; idx < 128 * 27; idx += 256) {
        int px = idx / 27, e = idx - px * 27;
        int k = e / 3, r = e - 3 * k;
        int src = (r < 2) ? (2 * k + r) : (18 + k);
        float v = outs[src * 136 + px] + __ldg(b_om + src);
        if (r == 2) v = 2.f / (1.f + expf(-v));
        dst[px * 27 + e] = v;
    }
}

// ---------------------------------------------------------------------------
// deform gather (fp16, per-thread form)
// ---------------------------------------------------------------------------
__device__ __forceinline__ void dgather32h(const __half* __restrict__ xb,
                                           const float* __restrict__ omrow,
                                           __half* __restrict__ dst,
                                           int h, int w0, int tap,
                                           int pg, int oct) {
    int ty = h - 1 + tap / 3;
    int txoff = tap % 3 - 1;
    const float* o3 = omrow + pg * 27 + tap * 3;
    float offy = __ldg(o3), offx = __ldg(o3 + 1), msk = __ldg(o3 + 2);
    float py = (float)ty + offy;
    float px = (float)(w0 + pg + txoff) + offx;
    float y0f = floorf(py), x0f = floorf(px);
    float ly = py - y0f, lx = px - x0f;
    int y0 = (int)y0f, x0 = (int)x0f;
    float wq[4] = {(1.f - ly) * (1.f - lx) * msk, (1.f - ly) * lx * msk,
                   ly * (1.f - lx) * msk,          ly * lx * msk};
    int ys[2] = {y0, y0 + 1};
    int xs[2] = {x0, x0 + 1};
    bool yok[2] = {(y0 >= 0) & (y0 < HH), (y0 + 1 >= 0) & (y0 + 1 < HH)};
    bool xok[2] = {(x0 >= 0) & (x0 < WW), (x0 + 1 >= 0) & (x0 + 1 < WW)};

    float u[8];
    #pragma unroll
    for (int j = 0; j < 8; ++j) u[j] = 0.f;

    #pragma unroll
    for (int sy = 0; sy < 2; ++sy) {
        #pragma unroll
        for (int sx = 0; sx < 2; ++sx) {
            if (yok[sy] && xok[sx]) {
                uint4 raw = __ldg((const uint4*)(xb +
                    ((size_t)(ys[sy] * WW + xs[sx])) * CC + oct * 8));
                float w = wq[sy * 2 + sx];
                const __half2* hp = (const __half2*)&raw;
                #pragma unroll
                for (int q = 0; q < 4; ++q) {
                    float2 f = __half22float2(hp[q]);
                    u[2 * q]     += w * f.x;
                    u[2 * q + 1] += w * f.y;
                }
            }
        }
    }
    __align__(16) __half2 p[4];
    #pragma unroll
    for (int q = 0; q < 4; ++q) p[q] = __floats2half2_rn(u[2 * q], u[2 * q + 1]);
    *(uint4*)&dst[pg * 72 + oct * 8] = *(const uint4*)p;
}

// ---------------------------------------------------------------------------
// Kernel B: modulated deformable conv 64->64, fp16 m16n8k16 + ldmatrix.
// 32-px tiles (4096 blocks). NOW 6 blocks/SM (reg-capped at 42).
// ---------------------------------------------------------------------------
#define B_SMEM_BYTES ((2*32*72 + 2*64*72) * 2)
__global__ __launch_bounds__(256, 6) void deform_kernel(const float* __restrict__ b_dc) {
    extern __shared__ __half smh[];
    __half* sval = smh;                  // [2][32][72]
    __half* swk  = smh + 2 * 32 * 72;    // [2][64][72]

    int tid = threadIdx.x;
    int blk = blockIdx.x;
    int b = blk >> 9;
    int rem = blk & 511;
    int h = rem >> 2;
    int w0 = (rem & 3) * 32;

    int lane = tid & 31, wid = tid >> 5;
    int warp_m = wid & 1;                // 2 x 16 px
    int warp_n = wid >> 1;               // 4 x 16 oc
    int lq = lane >> 2, lr = lane & 3;

    int aRowL = warp_m * 16 + (lane & 7) + ((lane >> 3) & 1) * 8;
    int aColL = ((lane >> 4) & 1) * 8;
    int bRowL = warp_n * 16 + ((lane >> 4) & 1) * 8 + (lane & 7);
    int bColL = ((lane >> 3) & 1) * 8;

    int oct = tid & 7;
    int pg  = tid >> 3;
    const __half* xb = g_xh + (size_t)b * HWs * CC;
    const float* omrow = g_offmask + ((size_t)b * HWs + h * WW + w0) * 27;

    float4 acc[2];
    acc[0] = make_float4(0.f, 0.f, 0.f, 0.f);
    acc[1] = make_float4(0.f, 0.f, 0.f, 0.f);

    #pragma unroll
    for (int r = 0; r < 2; ++r) {
        int idx = tid + 256 * r;
        ((uint4*)swk)[(idx >> 3) * 9 + (idx & 7)] = ((const uint4*)g_wdcH)[idx];
    }
    dgather32h(xb, omrow, sval, h, w0, 0, pg, oct);
    __syncthreads();

    #pragma unroll 1
    for (int tap = 0; tap < KK; ++tap) {
        int cur = tap & 1, nxt = cur ^ 1;
        bool pre = tap < 8;

        const __half* sv = sval + cur * 32 * 72;
        const __half* wb = swk + cur * 64 * 72;
        uint32_t aAddr = smem_u32(&sv[aRowL * 72 + aColL]);
        uint32_t bAddr = smem_u32(&wb[bRowL * 72 + bColL]);
        #pragma unroll
        for (int ks = 0; ks < 4; ++ks) {
            uint32_t a[4], bq[4];
            ldsm_x4(a, aAddr + ks * 32);
            ldsm_x4(bq, bAddr + ks * 32);
            mma16(acc[0], a, bq);
            mma16(acc[1], a, bq + 2);
        }

        if (pre) {
            #pragma unroll
            for (int r = 0; r < 2; ++r) {
                int idx = tid + 256 * r;
                ((uint4*)(swk + nxt * 64 * 72))[(idx >> 3) * 9 + (idx & 7)] =
                    ((const uint4*)g_wdcH)[(tap + 1) * 512 + idx];
            }
            dgather32h(xb, omrow, sval + nxt * 32 * 72, h, w0, tap + 1, pg, oct);
        }
        __syncthreads();
    }

    // epilogue
    __half* outs = smh;
    {
        int px = warp_m * 16 + lq;
        #pragma unroll
        for (int nt = 0; nt < 2; ++nt) {
            int oc = warp_n * 16 + nt * 8 + 2 * lr;
            float b0 = __ldg(b_dc + oc), b1 = __ldg(b_dc + oc + 1);
            float4 v = acc[nt];
            float e0 = v.x + b0, e1 = v.y + b1, e2 = v.z + b0, e3 = v.w + b1;
            e0 = e0 > 0.f ? e0 : 0.2f * e0;
            e1 = e1 > 0.f ? e1 : 0.2f * e1;
            e2 = e2 > 0.f ? e2 : 0.2f * e2;
            e3 = e3 > 0.f ? e3 : 0.2f * e3;
            *(__half2*)&outs[px * 72 + oc]       = __floats2half2_rn(e0, e1);
            *(__half2*)&outs[(px + 8) * 72 + oc] = __floats2half2_rn(e2, e3);
        }
    }
    __syncthreads();
    {
        int p = tid >> 3, seg = tid & 7;
        uint4 v = *(const uint4*)&outs[p * 72 + seg * 8];
        *(uint4*)(g_acth + ((size_t)b * HWs + h * WW + w0 + p) * CC + seg * 8) = v;
    }
}

// ---------------------------------------------------------------------------
// Kernel C: 3x3 conv 64->64 on fp16 NHWC act, fp16 m16n8k16 tensor cores.
// 128-px row blocks, one sync/tap pipeline, bias + fp32 residual epilogue.
// (R13 proven version: 136 rows, launch_bounds(256,3))
// ---------------------------------------------------------------------------
#define C_SMEM_BYTES ((2*136*72 + 2*64*72) * 2)
__global__ __launch_bounds__(256, 3) void conv2_kernel(const float* __restrict__ x,
                                                       const float* __restrict__ b_c,
                                                       float* __restrict__ out) {
    extern __shared__ __half smh[];
    __half* sval = smh;                  // [2][136][72]
    __half* swk  = smh + 2 * 136 * 72;   // [2][64][72]

    int tid = threadIdx.x;
    int b = blockIdx.x >> 7;
    int h = blockIdx.x & 127;

    int lane = tid & 31, wid = tid >> 5;
    int warp_m = wid & 3;                // 4 x 32 px
    int warp_n = wid >> 2;               // 2 x 32 oc
    int lq = lane >> 2, lr = lane & 3;

    float4 acc[2][4];
    #pragma unroll
    for (int mt = 0; mt < 2; ++mt)
        #pragma unroll
        for (int nt = 0; nt < 4; ++nt) acc[mt][nt] = make_float4(0.f, 0.f, 0.f, 0.f);

    const __half* actb = g_acth + (size_t)b * HWs * CC;

    auto stage_row = [&](int y, __half* dstv) {
        bool yok = (y >= 0) & (y < HH);
        #pragma unroll
        for (int r = 0; r < 5; ++r) {
            int i = tid + 256 * r;
            if (i < 1040) {
                int jj = i >> 3, o = i & 7;
                int xg = jj - 1;
                uint4 v = make_uint4(0u, 0u, 0u, 0u);
                if (yok && xg >= 0 && xg < WW)
                    v = __ldg((const uint4*)(actb + ((size_t)y * WW + xg) * CC + o * 8));
                *(uint4*)&dstv[jj * 72 + o * 8] = v;
            }
        }
    };

    stage_row(h - 1, sval);
    #pragma unroll
    for (int r = 0; r < 2; ++r) {
        int idx = tid + 256 * r;
        ((uint4*)swk)[(idx >> 3) * 9 + (idx & 7)] = ((const uint4*)g_wcH)[idx];
    }
    __syncthreads();

    #pragma unroll 1
    for (int t = 0; t < KK; ++t) {
        int dy = t / 3, dx = t % 3;
        int wcur = t & 1, wnxt = wcur ^ 1;
        int abuf = dy & 1;
        bool pre = t < 8;

        const uint32_t* svw = (const uint32_t*)(sval + abuf * 136 * 72);
        const uint32_t* wbw = (const uint32_t*)(swk + wcur * 64 * 72);
        #pragma unroll
        for (int ks = 0; ks < 4; ++ks) {
            uint32_t a[2][4];
            #pragma unroll
            for (int mt = 0; mt < 2; ++mt) {
                int pxb = warp_m * 32 + mt * 16 + lq + dx;
                a[mt][0] = svw[pxb * 36 + ks * 8 + lr];
                a[mt][1] = svw[(pxb + 8) * 36 + ks * 8 + lr];
                a[mt][2] = svw[pxb * 36 + ks * 8 + lr + 4];
                a[mt][3] = svw[(pxb + 8) * 36 + ks * 8 + lr + 4];
            }
            uint32_t bw[4][2];
            #pragma unroll
            for (int nt = 0; nt < 4; ++nt) {
                int oc = warp_n * 32 + nt * 8 + lq;
                bw[nt][0] = wbw[oc * 36 + ks * 8 + lr];
                bw[nt][1] = wbw[oc * 36 + ks * 8 + lr + 4];
            }
            #pragma unroll
            for (int mt = 0; mt < 2; ++mt)
                #pragma unroll
                for (int nt = 0; nt < 4; ++nt)
                    mma16(acc[mt][nt], a[mt], bw[nt]);
        }

        if (dx == 0 && dy < 2)
            stage_row(h + dy, sval + (abuf ^ 1) * 136 * 72);
        if (pre) {
            #pragma unroll
            for (int r = 0; r < 2; ++r) {
                int idx = tid + 256 * r;
                ((uint4*)(swk + wnxt * 64 * 72))[(idx >> 3) * 9 + (idx & 7)] =
                    ((const uint4*)g_wcH)[(t + 1) * 512 + idx];
            }
        }
        __syncthreads();
    }

    float* outs = (float*)smh;
    #pragma unroll
    for (int mt = 0; mt < 2; ++mt) {
        #pragma unroll
        for (int nt = 0; nt < 4; ++nt) {
            int px = warp_m * 32 + mt * 16 + lq;
            int oc = warp_n * 32 + nt * 8 + 2 * lr;
            float b0 = __ldg(b_c + oc), b1 = __ldg(b_c + oc + 1);
            float4 v = acc[mt][nt];
            outs[oc * 136 + px]           = v.x + b0;
            outs[(oc + 1) * 136 + px]     = v.y + b1;
            outs[oc * 136 + px + 8]       = v.z + b0;
            outs[(oc + 1) * 136 + px + 8] = v.w + b1;
        }
    }
    __syncthreads();
    #pragma unroll
    for (int j2 = 0; j2 < 8; ++j2) {
        int idx = tid + 256 * j2;
        int oc = idx >> 5, pxq = idx & 31;
        size_t base = ((size_t)b * CC + oc) * HWs + h * WW + pxq * 4;
        float4 v = *(const float4*)&outs[oc * 136 + pxq * 4];
        float4 r = *(const float4*)(x + base);
        v.x += r.x; v.y += r.y; v.z += r.z; v.w += r.w;
        *(float4*)(out + base) = v;
    }
}

// ---------------------------------------------------------------------------
extern "C" void kernel_launch(void* const* d_in, const int* in_sizes, int n_in,
                              void* d_out, int out_size) {
    const float* x    = (const float*)d_in[0];
    const float* w_om = (const float*)d_in[1];
    const float* b_om = (const float*)d_in[2];
    const float* w_dc = (const float*)d_in[3];
    const float* b_dc = (const float*)d_in[4];
    const float* w_c  = (const float*)d_in[5];
    const float* b_c  = (const float*)d_in[6];
    float* out = (float*)d_out;

    cudaFuncSetAttribute(offmask_h, cudaFuncAttributeMaxDynamicSharedMemorySize,
                         OM_SMEM_BYTES);
    cudaFuncSetAttribute(deform_kernel, cudaFuncAttributeMaxDynamicSharedMemorySize,
                         B_SMEM_BYTES);
    cudaFuncSetAttribute(conv2_kernel, cudaFuncAttributeMaxDynamicSharedMemorySize,
                         C_SMEM_BYTES);

    wtrans_kernel<<<360, 256>>>(w_dc, w_c, w_om);
    transpose_kernel<<<BB * (HWs / 64), 256>>>(x);

    offmask_h<<<BB * HH, 256, OM_SMEM_BYTES>>>(b_om);

    deform_kernel<<<BB * HH * 4, 256, B_SMEM_BYTES>>>(b_dc);

    conv2_kernel<<<BB * HH, 256, C_SMEM_BYTES>>>(x, b_c, out);
}